// round 1
// baseline (speedup 1.0000x reference)
#include <cuda_runtime.h>
#include <math.h>

#define D   768
#define HH  12
#define HS  64
#define BB  8
#define TT  1024
#define TCC 256
#define FFD 3072
#define MQ  (BB*TT)    // 8192 rows
#define MKV (BB*TCC)   // 2048 rows
#define DD  (D*D)

// ---------------- scratch (device globals; no allocs allowed) ----------------
__device__ float g_ln [MQ*D];
__device__ float g_q  [MQ*D];
__device__ float g_k  [MQ*D];
__device__ float g_v  [MQ*D];
__device__ float g_x1 [MQ*D];
__device__ float g_x2 [MQ*D];
__device__ float g_ffh[MQ*FFD];
__device__ float g_wts[3*DD];  // repacked self-attn QKV weights
__device__ float g_wtc[3*DD];  // repacked cross-attn QKV weights

// ---------------- LayerNorm: one block per row, 256 threads ----------------
__global__ void ln_kernel(const float* __restrict__ x, const float* __restrict__ w,
                          const float* __restrict__ b, float* __restrict__ out) {
    int row = blockIdx.x;
    const float* xr = x + (size_t)row * D;
    int tid = threadIdx.x;
    float v0 = xr[tid], v1 = xr[tid + 256], v2 = xr[tid + 512];
    float s  = v0 + v1 + v2;
    float sq = v0*v0 + v1*v1 + v2*v2;

    __shared__ float red[34];
    #pragma unroll
    for (int o = 16; o; o >>= 1) {
        s  += __shfl_down_sync(0xffffffffu, s,  o);
        sq += __shfl_down_sync(0xffffffffu, sq, o);
    }
    int wid = tid >> 5, lid = tid & 31;
    if (lid == 0) { red[wid] = s; red[8 + wid] = sq; }
    __syncthreads();
    if (tid < 8) {
        s = red[tid]; sq = red[8 + tid];
        #pragma unroll
        for (int o = 4; o; o >>= 1) {
            s  += __shfl_down_sync(0xffu, s,  o);
            sq += __shfl_down_sync(0xffu, sq, o);
        }
        if (tid == 0) {
            float mu  = s * (1.0f / D);
            float var = sq * (1.0f / D) - mu * mu;
            red[32] = mu;
            red[33] = rsqrtf(var + 1e-5f);
        }
    }
    __syncthreads();
    float mu = red[32], inv = red[33];
    float* orow = out + (size_t)row * D;
    orow[tid      ] = (v0 - mu) * inv * w[tid      ] + b[tid      ];
    orow[tid + 256] = (v1 - mu) * inv * w[tid + 256] + b[tid + 256];
    orow[tid + 512] = (v2 - mu) * inv * w[tid + 512] + b[tid + 512];
}

// ------------- repack [H,D,HS] stacked QKV weights -> [K=D, N=D] row-major -------------
__global__ void repack_kernel(const float* __restrict__ Wq, const float* __restrict__ Wk,
                              const float* __restrict__ Wv, float* __restrict__ dst) {
    int i = blockIdx.x * blockDim.x + threadIdx.x;
    if (i >= 3 * DD) return;
    int m = i / DD;
    int r = i - m * DD;
    int k = r / D, n = r - (r / D) * D;
    const float* W = (m == 0) ? Wq : ((m == 1) ? Wk : Wv);
    // element (h=n>>6, d=k, e=n&63) at h*D*HS + d*HS + e
    dst[(size_t)m * DD + (size_t)k * D + n] = W[(size_t)(n >> 6) * (D * HS) + (size_t)k * HS + (n & 63)];
}

__device__ __forceinline__ float silu_f(float z) { return z / (1.0f + expf(-z)); }

// ---------------- tiled fp32 GEMM: C[M,N] = A[M,K] * B[K,N] + bias (+act)(+res) ----------------
// BM=128 BN=64 BK=16, 256 threads, 8x4 microtile per thread.
template<int ACT, bool RES>
__global__ __launch_bounds__(256, 2)
void gemm_kernel(const float* __restrict__ A, const float* __restrict__ Bm,
                 const float* __restrict__ bias, const float* __restrict__ res,
                 float* __restrict__ C, int M, int N, int K) {
    const int BM = 128, BN = 64, BK = 16;
    __shared__ float As[BK][BM + 4];   // transposed: As[k][m]
    __shared__ float Bs[BK][BN];

    int bm = blockIdx.y * BM, bn = blockIdx.x * BN;
    int t  = threadIdx.x;
    int tx = t & 15, ty = t >> 4;

    float acc[8][4];
    #pragma unroll
    for (int i = 0; i < 8; i++)
        #pragma unroll
        for (int j = 0; j < 4; j++) acc[i][j] = 0.0f;

    // A loader: thread t -> row t>>1, col-group (t&1)*8 (two float4)
    int arow = t >> 1;
    int ac0  = (t & 1) * 8;
    const float* Aptr = A + (size_t)(bm + arow) * K + ac0;
    // B loader: thread t -> k-row t>>4, 1 float4 at col (t&15)*4
    int bk = t >> 4, bc = (t & 15) * 4;
    const float* Bptr = Bm + (size_t)bk * N + bn + bc;

    for (int kt = 0; kt < K; kt += BK) {
        float4 a0 = *(const float4*)(Aptr);
        float4 a1 = *(const float4*)(Aptr + 4);
        Aptr += BK;
        As[ac0 + 0][arow] = a0.x; As[ac0 + 1][arow] = a0.y;
        As[ac0 + 2][arow] = a0.z; As[ac0 + 3][arow] = a0.w;
        As[ac0 + 4][arow] = a1.x; As[ac0 + 5][arow] = a1.y;
        As[ac0 + 6][arow] = a1.z; As[ac0 + 7][arow] = a1.w;

        float4 bv = *(const float4*)(Bptr);
        Bptr += (size_t)BK * N;
        *(float4*)&Bs[bk][bc] = bv;

        __syncthreads();
        #pragma unroll
        for (int k = 0; k < BK; k++) {
            float4 b0  = *(const float4*)&Bs[k][tx * 4];
            float4 av0 = *(const float4*)&As[k][ty * 8];
            float4 av1 = *(const float4*)&As[k][ty * 8 + 4];
            float am[8] = {av0.x, av0.y, av0.z, av0.w, av1.x, av1.y, av1.z, av1.w};
            float bm4[4] = {b0.x, b0.y, b0.z, b0.w};
            #pragma unroll
            for (int i = 0; i < 8; i++)
                #pragma unroll
                for (int j = 0; j < 4; j++)
                    acc[i][j] = fmaf(am[i], bm4[j], acc[i][j]);
        }
        __syncthreads();
    }

    int col0 = bn + tx * 4;
    float4 bv4 = *(const float4*)(bias + col0);
    #pragma unroll
    for (int i = 0; i < 8; i++) {
        size_t row = (size_t)(bm + ty * 8 + i);
        float4 o;
        o.x = acc[i][0] + bv4.x;
        o.y = acc[i][1] + bv4.y;
        o.z = acc[i][2] + bv4.z;
        o.w = acc[i][3] + bv4.w;
        if (ACT == 1) { o.x = silu_f(o.x); o.y = silu_f(o.y); o.z = silu_f(o.z); o.w = silu_f(o.w); }
        if (RES) {
            float4 rr = *(const float4*)(res + row * N + col0);
            o.x += rr.x; o.y += rr.y; o.z += rr.z; o.w += rr.w;
        }
        *(float4*)(C + row * N + col0) = o;
    }
}

// ---------------- attention: 1 query per thread, online softmax, fused residual ----------------
// grid: (Tq/128, H, B), block 128. out[row, h*64+e] = xres[row, h*64+e] + softmax(qK^T*s)V
__global__ __launch_bounds__(128, 2)
void attn_kernel(const float* __restrict__ Q, const float* __restrict__ Kb,
                 const float* __restrict__ Vb, const float* __restrict__ xres,
                 float* __restrict__ out, int Tq, int Tkv) {
    __shared__ float Ksh[64][HS];
    __shared__ float Vsh[64][HS];
    int qt = blockIdx.x, h = blockIdx.y, b = blockIdx.z;
    int t = threadIdx.x;
    int qrow = b * Tq + qt * 128 + t;
    const float* qp = Q + (size_t)qrow * D + h * HS;

    const float SC = 0.125f * 1.4426950408889634f;  // HS^-0.5 * log2(e)
    float q[HS];
    #pragma unroll
    for (int i4 = 0; i4 < 16; i4++) {
        float4 v4 = *(const float4*)(qp + i4 * 4);
        q[i4*4+0] = v4.x * SC; q[i4*4+1] = v4.y * SC;
        q[i4*4+2] = v4.z * SC; q[i4*4+3] = v4.w * SC;
    }
    float m2 = -1e30f, l = 0.0f;
    float acc[HS];
    #pragma unroll
    for (int i = 0; i < HS; i++) acc[i] = 0.0f;

    int r  = t >> 1;
    int cb = (t & 1) * 32;

    for (int kt = 0; kt < Tkv; kt += 64) {
        size_t kvrow = (size_t)(b * Tkv + kt + r);
        const float* kp = Kb + kvrow * D + h * HS + cb;
        const float* vp = Vb + kvrow * D + h * HS + cb;
        #pragma unroll
        for (int i = 0; i < 8; i++) {
            *(float4*)&Ksh[r][cb + i * 4] = *(const float4*)(kp + i * 4);
            *(float4*)&Vsh[r][cb + i * 4] = *(const float4*)(vp + i * 4);
        }
        __syncthreads();

        #pragma unroll 1
        for (int j = 0; j < 64; j++) {
            float s0 = 0.f, s1 = 0.f, s2 = 0.f, s3 = 0.f;
            #pragma unroll
            for (int i4 = 0; i4 < 16; i4++) {
                float4 kk = *(const float4*)&Ksh[j][i4 * 4];
                s0 = fmaf(q[i4*4+0], kk.x, s0);
                s1 = fmaf(q[i4*4+1], kk.y, s1);
                s2 = fmaf(q[i4*4+2], kk.z, s2);
                s3 = fmaf(q[i4*4+3], kk.w, s3);
            }
            float s = (s0 + s1) + (s2 + s3);
            if (s > m2) {  // rare after first few keys
                float corr = exp2f(m2 - s);
                m2 = s;
                l *= corr;
                #pragma unroll
                for (int i = 0; i < HS; i++) acc[i] *= corr;
            }
            float p = exp2f(s - m2);
            l += p;
            #pragma unroll
            for (int i4 = 0; i4 < 16; i4++) {
                float4 vv = *(const float4*)&Vsh[j][i4 * 4];
                acc[i4*4+0] = fmaf(p, vv.x, acc[i4*4+0]);
                acc[i4*4+1] = fmaf(p, vv.y, acc[i4*4+1]);
                acc[i4*4+2] = fmaf(p, vv.z, acc[i4*4+2]);
                acc[i4*4+3] = fmaf(p, vv.w, acc[i4*4+3]);
            }
        }
        __syncthreads();
    }

    float inv = 1.0f / l;
    const float* rp = xres + (size_t)qrow * D + h * HS;
    float* op = out + (size_t)qrow * D + h * HS;
    #pragma unroll
    for (int i4 = 0; i4 < 16; i4++) {
        float4 rr = *(const float4*)(rp + i4 * 4);
        float4 o;
        o.x = rr.x + acc[i4*4+0] * inv;
        o.y = rr.y + acc[i4*4+1] * inv;
        o.z = rr.z + acc[i4*4+2] * inv;
        o.w = rr.w + acc[i4*4+3] * inv;
        *(float4*)(op + i4 * 4) = o;
    }
}

// ---------------- host launch ----------------
extern "C" void kernel_launch(void* const* d_in, const int* in_sizes, int n_in,
                              void* d_out, int out_size) {
    const float* x0    = (const float*)d_in[0];
    const float* ctx   = (const float*)d_in[1];
    const float* ln1_w = (const float*)d_in[2];
    const float* ln1_b = (const float*)d_in[3];
    const float* sWq   = (const float*)d_in[4];
    const float* sbq   = (const float*)d_in[5];
    const float* sWk   = (const float*)d_in[6];
    const float* sbk   = (const float*)d_in[7];
    const float* sWv   = (const float*)d_in[8];
    const float* sbv   = (const float*)d_in[9];
    const float* ln2_w = (const float*)d_in[10];
    const float* ln2_b = (const float*)d_in[11];
    const float* cWq   = (const float*)d_in[12];
    const float* cbq   = (const float*)d_in[13];
    const float* cWk   = (const float*)d_in[14];
    const float* cbk   = (const float*)d_in[15];
    const float* cWv   = (const float*)d_in[16];
    const float* cbv   = (const float*)d_in[17];
    const float* ln3_w = (const float*)d_in[18];
    const float* ln3_b = (const float*)d_in[19];
    const float* W1    = (const float*)d_in[20];
    const float* b1    = (const float*)d_in[21];
    const float* W2    = (const float*)d_in[22];
    const float* b2    = (const float*)d_in[23];
    float* outp = (float*)d_out;

    float *ln, *q, *k, *v, *x1, *x2, *ffh, *wts, *wtc;
    cudaGetSymbolAddress((void**)&ln,  g_ln);
    cudaGetSymbolAddress((void**)&q,   g_q);
    cudaGetSymbolAddress((void**)&k,   g_k);
    cudaGetSymbolAddress((void**)&v,   g_v);
    cudaGetSymbolAddress((void**)&x1,  g_x1);
    cudaGetSymbolAddress((void**)&x2,  g_x2);
    cudaGetSymbolAddress((void**)&ffh, g_ffh);
    cudaGetSymbolAddress((void**)&wts, g_wts);
    cudaGetSymbolAddress((void**)&wtc, g_wtc);

    dim3 gproj(D / 64, MQ / 128);       // N=768, M=8192
    dim3 gkv  (D / 64, MKV / 128);      // N=768, M=2048
    dim3 gff1 (FFD / 64, MQ / 128);     // N=3072
    dim3 gff2 (D / 64, MQ / 128);

    // ---- block 1: self attention ----
    ln_kernel<<<MQ, 256>>>(x0, ln1_w, ln1_b, ln);
    repack_kernel<<<(3 * DD + 255) / 256, 256>>>(sWq, sWk, sWv, wts);
    gemm_kernel<0, false><<<gproj, 256>>>(ln, wts,          sbq, nullptr, q, MQ, D, D);
    gemm_kernel<0, false><<<gproj, 256>>>(ln, wts + DD,     sbk, nullptr, k, MQ, D, D);
    gemm_kernel<0, false><<<gproj, 256>>>(ln, wts + 2 * DD, sbv, nullptr, v, MQ, D, D);
    attn_kernel<<<dim3(TT / 128, HH, BB), 128>>>(q, k, v, x0, x1, TT, TT);

    // ---- block 2: cross attention ----
    ln_kernel<<<MQ, 256>>>(x1, ln2_w, ln2_b, ln);
    repack_kernel<<<(3 * DD + 255) / 256, 256>>>(cWq, cWk, cWv, wtc);
    gemm_kernel<0, false><<<gproj, 256>>>(ln,  wtc,          cbq, nullptr, q, MQ,  D, D);
    gemm_kernel<0, false><<<gkv,   256>>>(ctx, wtc + DD,     cbk, nullptr, k, MKV, D, D);
    gemm_kernel<0, false><<<gkv,   256>>>(ctx, wtc + 2 * DD, cbv, nullptr, v, MKV, D, D);
    attn_kernel<<<dim3(TT / 128, HH, BB), 128>>>(q, k, v, x1, x2, TT, TCC);

    // ---- block 3: FFN ----
    ln_kernel<<<MQ, 256>>>(x2, ln3_w, ln3_b, ln);
    gemm_kernel<1, false><<<gff1, 256>>>(ln,  W1, b1, nullptr, ffh,  MQ, FFD, D);
    gemm_kernel<0, true ><<<gff2, 256>>>(ffh, W2, b2, x2,      outp, MQ, D, FFD);
}

// round 3
// speedup vs baseline: 1.8066x; 1.8066x over previous
#include <cuda_runtime.h>
#include <math.h>
#include <stdint.h>

#define D   768
#define HH  12
#define HS  64
#define BB  8
#define TT  1024
#define TCC 256
#define FFD 3072
#define MQ  (BB*TT)    // 8192 rows
#define MKV (BB*TCC)   // 2048 rows
#define DD  (D*D)

// ---------------- scratch (device globals; no allocs allowed) ----------------
__device__ float g_ln [MQ*D];
__device__ float g_q  [MQ*D];
__device__ float g_k  [MQ*D];
__device__ float g_v  [MQ*D];
__device__ float g_x1 [MQ*D];
__device__ float g_x2 [MQ*D];
__device__ float g_ctx[MKV*D];           // tf32-rounded context
__device__ float g_ffh[(size_t)MQ*FFD];
__device__ float g_wts[3*DD];            // repacked self-attn QKV weights [N,K]
__device__ float g_wtc[3*DD];            // repacked cross-attn QKV weights [N,K]
__device__ float g_w1t[(size_t)FFD*D];   // W1^T : [FF, D]
__device__ float g_w2t[(size_t)D*FFD];   // W2^T : [D, FF]

// ---------------- helpers ----------------
__device__ __forceinline__ uint32_t smem_u32(const void* p) {
    uint32_t a;
    asm("{ .reg .u64 t; cvta.to.shared.u64 t, %1; cvt.u32.u64 %0, t; }" : "=r"(a) : "l"(p));
    return a;
}
__device__ __forceinline__ float f2tf_f(float f) {
    uint32_t r; asm("cvt.rna.tf32.f32 %0, %1;" : "=r"(r) : "f"(f));
    return __uint_as_float(r);
}
__device__ __forceinline__ void cp_async16(uint32_t dst, const void* src) {
    asm volatile("cp.async.cg.shared.global [%0], [%1], 16;" :: "r"(dst), "l"(src));
}
__device__ __forceinline__ void cp_commit() { asm volatile("cp.async.commit_group;"); }
template<int N> __device__ __forceinline__ void cp_wait() {
    asm volatile("cp.async.wait_group %0;" :: "n"(N));
}
__device__ __forceinline__ void mma_tf32(float* c, const uint32_t* a, const uint32_t* b) {
    asm volatile("mma.sync.aligned.m16n8k8.row.col.f32.tf32.tf32.f32 "
        "{%0,%1,%2,%3}, {%4,%5,%6,%7}, {%8,%9}, {%0,%1,%2,%3};"
        : "+f"(c[0]), "+f"(c[1]), "+f"(c[2]), "+f"(c[3])
        : "r"(a[0]), "r"(a[1]), "r"(a[2]), "r"(a[3]), "r"(b[0]), "r"(b[1]));
}
__device__ __forceinline__ float silu_f(float z) { return z / (1.0f + expf(-z)); }

// ---------------- LayerNorm (tf32-rounded output; feeds GEMM A) ----------------
__global__ void ln_kernel(const float* __restrict__ x, const float* __restrict__ w,
                          const float* __restrict__ b, float* __restrict__ out) {
    int row = blockIdx.x;
    const float* xr = x + (size_t)row * D;
    int tid = threadIdx.x;
    float v0 = xr[tid], v1 = xr[tid + 256], v2 = xr[tid + 512];
    float s  = v0 + v1 + v2;
    float sq = v0*v0 + v1*v1 + v2*v2;

    __shared__ float red[34];
    #pragma unroll
    for (int o = 16; o; o >>= 1) {
        s  += __shfl_down_sync(0xffffffffu, s,  o);
        sq += __shfl_down_sync(0xffffffffu, sq, o);
    }
    int wid = tid >> 5, lid = tid & 31;
    if (lid == 0) { red[wid] = s; red[8 + wid] = sq; }
    __syncthreads();
    if (tid < 8) {
        s = red[tid]; sq = red[8 + tid];
        #pragma unroll
        for (int o = 4; o; o >>= 1) {
            s  += __shfl_down_sync(0xffu, s,  o);
            sq += __shfl_down_sync(0xffu, sq, o);
        }
        if (tid == 0) {
            float mu  = s * (1.0f / D);
            float var = sq * (1.0f / D) - mu * mu;
            red[32] = mu;
            red[33] = rsqrtf(var + 1e-5f);
        }
    }
    __syncthreads();
    float mu = red[32], inv = red[33];
    float* orow = out + (size_t)row * D;
    orow[tid      ] = f2tf_f((v0 - mu) * inv * w[tid      ] + b[tid      ]);
    orow[tid + 256] = f2tf_f((v1 - mu) * inv * w[tid + 256] + b[tid + 256]);
    orow[tid + 512] = f2tf_f((v2 - mu) * inv * w[tid + 512] + b[tid + 512]);
}

// ------------- repack [H,D,HS] QKV weights -> [N=D rows, K=D] k-major, tf32 -------------
__global__ void repack_kernel(const float* __restrict__ Wq, const float* __restrict__ Wk,
                              const float* __restrict__ Wv, float* __restrict__ dst) {
    int i = blockIdx.x * blockDim.x + threadIdx.x;
    if (i >= 3 * DD) return;
    int m = i / DD;
    int r = i - m * DD;
    int n = r / D, k = r - n * D;
    const float* W = (m == 0) ? Wq : ((m == 1) ? Wk : Wv);
    dst[(size_t)m * DD + (size_t)n * D + k] =
        f2tf_f(W[(size_t)(n >> 6) * (D * HS) + (size_t)k * HS + (n & 63)]);
}

// ------------- tiled transpose + tf32 round: dst[c*R + r] = src[r*C + c] -------------
__global__ void transpose_kernel(const float* __restrict__ src, float* __restrict__ dst,
                                 int R, int C) {
    __shared__ float tile[32][33];
    int bx = blockIdx.x * 32, by = blockIdx.y * 32;
    int x = bx + threadIdx.x;
    #pragma unroll
    for (int i = 0; i < 32; i += 8)
        tile[threadIdx.y + i][threadIdx.x] = src[(size_t)(by + threadIdx.y + i) * C + x];
    __syncthreads();
    int x2 = by + threadIdx.x;
    #pragma unroll
    for (int i = 0; i < 32; i += 8)
        dst[(size_t)(bx + threadIdx.y + i) * R + x2] = f2tf_f(tile[threadIdx.x][threadIdx.y + i]);
}

// ------------- elementwise tf32 round -------------
__global__ void round_kernel(const float* __restrict__ src, float* __restrict__ dst, int n) {
    int i = blockIdx.x * blockDim.x + threadIdx.x;
    if (i < n) dst[i] = f2tf_f(src[i]);
}

// =======================================================================================
// tf32 mma.sync GEMM: C[M,N] = A[M,K] * Bt[N,K]^T + bias (+SiLU)(+res)(+tf32 round)
// BM=BN=128, BK=32, 256 threads (8 warps x 64x32 tiles), 4-stage cp.async pipeline.
// A, Bt must already hold tf32-rounded fp32 values.
// =======================================================================================
#define BKk    32
#define RSTR   36                  // padded row stride (floats) -> conflict-free frags
#define STAGES 4
#define TILEW  (128 * RSTR)        // floats per stage per operand

template<int ACT, bool RES, bool TFOUT>
__global__ __launch_bounds__(256)
void gemm_mma(const float* __restrict__ A, const float* __restrict__ Bt,
              const float* __restrict__ bias, const float* __restrict__ res,
              float* __restrict__ C, int M, int N, int K) {
    extern __shared__ float sm[];
    float* As = sm;                      // [STAGES][128][RSTR]
    float* Bs = sm + STAGES * TILEW;     // [STAGES][128][RSTR]

    const int tid  = threadIdx.x;
    const int lane = tid & 31, wid = tid >> 5;
    const int warp_m = wid & 1, warp_n = wid >> 1;       // 2 x 4 warps
    const int bm = blockIdx.y * 128, bn = blockIdx.x * 128;

    const int lrow = tid >> 3;           // loader: 0..31 rows handled per pass
    const int lch  = tid & 7;            // chunk (16B) within row
    const uint32_t sbase = smem_u32(sm);

    const float* Ag = A + (size_t)(bm + lrow) * K + lch * 4;
    const float* Bg = Bt + (size_t)(bn + lrow) * K + lch * 4;

    const int nt = K >> 5;

    auto prefetch = [&](int kt) {
        int s = kt % STAGES;
        uint32_t adst = sbase + (uint32_t)(s * TILEW + lrow * RSTR + lch * 4) * 4u;
        uint32_t bdst = sbase + (uint32_t)((STAGES + s) * TILEW + lrow * RSTR + lch * 4) * 4u;
        const float* ag = Ag + kt * BKk;
        const float* bg = Bg + kt * BKk;
        #pragma unroll
        for (int i = 0; i < 4; i++) {   // 4 passes of 32 rows
            cp_async16(adst + (uint32_t)(i * 32 * RSTR) * 4u, ag + (size_t)(i * 32) * K);
            cp_async16(bdst + (uint32_t)(i * 32 * RSTR) * 4u, bg + (size_t)(i * 32) * K);
        }
    };

    float acc[4][4][4];
    #pragma unroll
    for (int mi = 0; mi < 4; mi++)
        #pragma unroll
        for (int ni = 0; ni < 4; ni++)
            #pragma unroll
            for (int e = 0; e < 4; e++) acc[mi][ni][e] = 0.0f;

    // prologue: prefetch STAGES-1 tiles
    #pragma unroll
    for (int s = 0; s < STAGES - 1; s++) { prefetch(s); cp_commit(); }

    const int lr = lane >> 2, lc = lane & 3;
    const int am0 = warp_m * 64 + lr;          // A frag base row within tile
    const int bn0 = warp_n * 32 + lr;          // B frag base n within tile (lr = lane>>2 = col group)

    for (int kt = 0; kt < nt; kt++) {
        cp_wait<STAGES - 2>();
        __syncthreads();

        int s = kt % STAGES;
        const uint32_t* Asx = (const uint32_t*)(As + s * TILEW);
        const uint32_t* Bsx = (const uint32_t*)(Bs + s * TILEW);

        #pragma unroll
        for (int ks = 0; ks < 4; ks++) {
            int k0 = ks * 8;
            uint32_t af[4][4], bf[4][2];
            #pragma unroll
            for (int mi = 0; mi < 4; mi++) {
                int r = am0 + mi * 16;
                af[mi][0] = Asx[r * RSTR + k0 + lc];
                af[mi][1] = Asx[(r + 8) * RSTR + k0 + lc];
                af[mi][2] = Asx[r * RSTR + k0 + lc + 4];
                af[mi][3] = Asx[(r + 8) * RSTR + k0 + lc + 4];
            }
            #pragma unroll
            for (int ni = 0; ni < 4; ni++) {
                int n = bn0 + ni * 8;
                bf[ni][0] = Bsx[n * RSTR + k0 + lc];
                bf[ni][1] = Bsx[n * RSTR + k0 + lc + 4];
            }
            #pragma unroll
            for (int mi = 0; mi < 4; mi++)
                #pragma unroll
                for (int ni = 0; ni < 4; ni++)
                    mma_tf32(acc[mi][ni], af[mi], bf[ni]);
        }

        __syncthreads();
        if (kt + STAGES - 1 < nt) prefetch(kt + STAGES - 1);
        cp_commit();
    }

    // ---- epilogue: fused bias / SiLU / residual / tf32-round, float2 stores ----
    #pragma unroll
    for (int mi = 0; mi < 4; mi++) {
        int r0 = bm + warp_m * 64 + mi * 16 + lr;
        #pragma unroll
        for (int ni = 0; ni < 4; ni++) {
            int c0 = bn + warp_n * 32 + ni * 8 + 2 * lc;
            float b0 = bias[c0], b1 = bias[c0 + 1];
            float v00 = acc[mi][ni][0] + b0, v01 = acc[mi][ni][1] + b1;
            float v10 = acc[mi][ni][2] + b0, v11 = acc[mi][ni][3] + b1;
            if (ACT == 1) { v00 = silu_f(v00); v01 = silu_f(v01); v10 = silu_f(v10); v11 = silu_f(v11); }
            if (RES) {
                const float2 rA = *(const float2*)(res + (size_t)r0 * N + c0);
                const float2 rB = *(const float2*)(res + (size_t)(r0 + 8) * N + c0);
                v00 += rA.x; v01 += rA.y; v10 += rB.x; v11 += rB.y;
            }
            if (TFOUT) { v00 = f2tf_f(v00); v01 = f2tf_f(v01); v10 = f2tf_f(v10); v11 = f2tf_f(v11); }
            *(float2*)(C + (size_t)r0 * N + c0)       = make_float2(v00, v01);
            *(float2*)(C + (size_t)(r0 + 8) * N + c0) = make_float2(v10, v11);
        }
    }
}

// ---------------- attention: 1 query per thread, online softmax, fused residual ----------------
__global__ __launch_bounds__(128, 2)
void attn_kernel(const float* __restrict__ Q, const float* __restrict__ Kb,
                 const float* __restrict__ Vb, const float* __restrict__ xres,
                 float* __restrict__ out, int Tq, int Tkv) {
    __shared__ float Ksh[64][HS];
    __shared__ float Vsh[64][HS];
    int qt = blockIdx.x, h = blockIdx.y, b = blockIdx.z;
    int t = threadIdx.x;
    int qrow = b * Tq + qt * 128 + t;
    const float* qp = Q + (size_t)qrow * D + h * HS;

    const float SC = 0.125f * 1.4426950408889634f;
    float q[HS];
    #pragma unroll
    for (int i4 = 0; i4 < 16; i4++) {
        float4 v4 = *(const float4*)(qp + i4 * 4);
        q[i4*4+0] = v4.x * SC; q[i4*4+1] = v4.y * SC;
        q[i4*4+2] = v4.z * SC; q[i4*4+3] = v4.w * SC;
    }
    float m2 = -1e30f, l = 0.0f;
    float acc[HS];
    #pragma unroll
    for (int i = 0; i < HS; i++) acc[i] = 0.0f;

    int r  = t >> 1;
    int cb = (t & 1) * 32;

    for (int kt = 0; kt < Tkv; kt += 64) {
        size_t kvrow = (size_t)(b * Tkv + kt + r);
        const float* kp = Kb + kvrow * D + h * HS + cb;
        const float* vp = Vb + kvrow * D + h * HS + cb;
        #pragma unroll
        for (int i = 0; i < 8; i++) {
            *(float4*)&Ksh[r][cb + i * 4] = *(const float4*)(kp + i * 4);
            *(float4*)&Vsh[r][cb + i * 4] = *(const float4*)(vp + i * 4);
        }
        __syncthreads();

        #pragma unroll 1
        for (int j = 0; j < 64; j++) {
            float s0 = 0.f, s1 = 0.f, s2 = 0.f, s3 = 0.f;
            #pragma unroll
            for (int i4 = 0; i4 < 16; i4++) {
                float4 kk = *(const float4*)&Ksh[j][i4 * 4];
                s0 = fmaf(q[i4*4+0], kk.x, s0);
                s1 = fmaf(q[i4*4+1], kk.y, s1);
                s2 = fmaf(q[i4*4+2], kk.z, s2);
                s3 = fmaf(q[i4*4+3], kk.w, s3);
            }
            float s = (s0 + s1) + (s2 + s3);
            if (s > m2) {
                float corr = exp2f(m2 - s);
                m2 = s;
                l *= corr;
                #pragma unroll
                for (int i = 0; i < HS; i++) acc[i] *= corr;
            }
            float p = exp2f(s - m2);
            l += p;
            #pragma unroll
            for (int i4 = 0; i4 < 16; i4++) {
                float4 vv = *(const float4*)&Vsh[j][i4 * 4];
                acc[i4*4+0] = fmaf(p, vv.x, acc[i4*4+0]);
                acc[i4*4+1] = fmaf(p, vv.y, acc[i4*4+1]);
                acc[i4*4+2] = fmaf(p, vv.z, acc[i4*4+2]);
                acc[i4*4+3] = fmaf(p, vv.w, acc[i4*4+3]);
            }
        }
        __syncthreads();
    }

    float inv = 1.0f / l;
    const float* rp = xres + (size_t)qrow * D + h * HS;
    float* op = out + (size_t)qrow * D + h * HS;
    #pragma unroll
    for (int i4 = 0; i4 < 16; i4++) {
        float4 rr = *(const float4*)(rp + i4 * 4);
        float4 o;
        o.x = rr.x + acc[i4*4+0] * inv;
        o.y = rr.y + acc[i4*4+1] * inv;
        o.z = rr.z + acc[i4*4+2] * inv;
        o.w = rr.w + acc[i4*4+3] * inv;
        *(float4*)(op + i4 * 4) = o;
    }
}

// ---------------- host launch ----------------
extern "C" void kernel_launch(void* const* d_in, const int* in_sizes, int n_in,
                              void* d_out, int out_size) {
    const float* x0    = (const float*)d_in[0];
    const float* ctx   = (const float*)d_in[1];
    const float* ln1_w = (const float*)d_in[2];
    const float* ln1_b = (const float*)d_in[3];
    const float* sWq   = (const float*)d_in[4];
    const float* sbq   = (const float*)d_in[5];
    const float* sWk   = (const float*)d_in[6];
    const float* sbk   = (const float*)d_in[7];
    const float* sWv   = (const float*)d_in[8];
    const float* sbv   = (const float*)d_in[9];
    const float* ln2_w = (const float*)d_in[10];
    const float* ln2_b = (const float*)d_in[11];
    const float* cWq   = (const float*)d_in[12];
    const float* cbq   = (const float*)d_in[13];
    const float* cWk   = (const float*)d_in[14];
    const float* cbk   = (const float*)d_in[15];
    const float* cWv   = (const float*)d_in[16];
    const float* cbv   = (const float*)d_in[17];
    const float* ln3_w = (const float*)d_in[18];
    const float* ln3_b = (const float*)d_in[19];
    const float* W1    = (const float*)d_in[20];
    const float* b1    = (const float*)d_in[21];
    const float* W2    = (const float*)d_in[22];
    const float* b2    = (const float*)d_in[23];
    float* outp = (float*)d_out;

    float *ln, *q, *k, *v, *x1, *x2, *ctr, *ffh, *wts, *wtc, *w1t, *w2t;
    cudaGetSymbolAddress((void**)&ln,  g_ln);
    cudaGetSymbolAddress((void**)&q,   g_q);
    cudaGetSymbolAddress((void**)&k,   g_k);
    cudaGetSymbolAddress((void**)&v,   g_v);
    cudaGetSymbolAddress((void**)&x1,  g_x1);
    cudaGetSymbolAddress((void**)&x2,  g_x2);
    cudaGetSymbolAddress((void**)&ctr, g_ctx);
    cudaGetSymbolAddress((void**)&ffh, g_ffh);
    cudaGetSymbolAddress((void**)&wts, g_wts);
    cudaGetSymbolAddress((void**)&wtc, g_wtc);
    cudaGetSymbolAddress((void**)&w1t, g_w1t);
    cudaGetSymbolAddress((void**)&w2t, g_w2t);

    const int SMEM_DYN = STAGES * TILEW * 2 * 4;  // 147456 B
    static int attr_done = 0;
    cudaFuncSetAttribute(gemm_mma<0, false, false>, cudaFuncAttributeMaxDynamicSharedMemorySize, SMEM_DYN);
    cudaFuncSetAttribute(gemm_mma<1, false, true >, cudaFuncAttributeMaxDynamicSharedMemorySize, SMEM_DYN);
    cudaFuncSetAttribute(gemm_mma<0, true,  false>, cudaFuncAttributeMaxDynamicSharedMemorySize, SMEM_DYN);
    (void)attr_done;

    dim3 gproj(D / 128, MQ / 128);      // (6, 64)
    dim3 gkv  (D / 128, MKV / 128);     // (6, 16)
    dim3 gff1 (FFD / 128, MQ / 128);    // (24, 64)
    dim3 gff2 (D / 128, MQ / 128);      // (6, 64)

    // weight / input preprocessing (tf32 rounding at producers)
    repack_kernel<<<(3 * DD + 255) / 256, 256>>>(sWq, sWk, sWv, wts);
    repack_kernel<<<(3 * DD + 255) / 256, 256>>>(cWq, cWk, cWv, wtc);
    transpose_kernel<<<dim3(FFD / 32, D / 32), dim3(32, 8)>>>(W1, w1t, D, FFD);
    transpose_kernel<<<dim3(D / 32, FFD / 32), dim3(32, 8)>>>(W2, w2t, FFD, D);
    round_kernel<<<(MKV * D + 255) / 256, 256>>>(ctx, ctr, MKV * D);

    // ---- block 1: self attention ----
    ln_kernel<<<MQ, 256>>>(x0, ln1_w, ln1_b, ln);
    gemm_mma<0, false, false><<<gproj, 256, SMEM_DYN>>>(ln, wts,          sbq, nullptr, q, MQ, D, D);
    gemm_mma<0, false, false><<<gproj, 256, SMEM_DYN>>>(ln, wts + DD,     sbk, nullptr, k, MQ, D, D);
    gemm_mma<0, false, false><<<gproj, 256, SMEM_DYN>>>(ln, wts + 2 * DD, sbv, nullptr, v, MQ, D, D);
    attn_kernel<<<dim3(TT / 128, HH, BB), 128>>>(q, k, v, x0, x1, TT, TT);

    // ---- block 2: cross attention ----
    ln_kernel<<<MQ, 256>>>(x1, ln2_w, ln2_b, ln);
    gemm_mma<0, false, false><<<gproj, 256, SMEM_DYN>>>(ln,  wtc,          cbq, nullptr, q, MQ,  D, D);
    gemm_mma<0, false, false><<<gkv,   256, SMEM_DYN>>>(ctr, wtc + DD,     cbk, nullptr, k, MKV, D, D);
    gemm_mma<0, false, false><<<gkv,   256, SMEM_DYN>>>(ctr, wtc + 2 * DD, cbv, nullptr, v, MKV, D, D);
    attn_kernel<<<dim3(TT / 128, HH, BB), 128>>>(q, k, v, x1, x2, TT, TCC);

    // ---- block 3: FFN ----
    ln_kernel<<<MQ, 256>>>(x2, ln3_w, ln3_b, ln);
    gemm_mma<1, false, true ><<<gff1, 256, SMEM_DYN>>>(ln,  w1t, b1, nullptr, ffh,  MQ, FFD, D);
    gemm_mma<0, true,  false><<<gff2, 256, SMEM_DYN>>>(ffh, w2t, b2, x2,      outp, MQ, D, FFD);
}

// round 4
// speedup vs baseline: 3.5428x; 1.9610x over previous
#include <cuda_runtime.h>
#include <math.h>
#include <stdint.h>

#define D   768
#define HH  12
#define HS  64
#define BB  8
#define TT  1024
#define TCC 256
#define FFD 3072
#define MQ  (BB*TT)    // 8192 rows
#define MKV (BB*TCC)   // 2048 rows
#define DD  (D*D)

// ---------------- scratch (device globals; no allocs allowed) ----------------
__device__ float g_ln [MQ*D];
__device__ float g_q  [MQ*D];                 // cross-attn Q
__device__ float g_qkv[(size_t)MQ*3*D];       // self-attn fused QKV [8192 x 2304]
__device__ float g_kvc[(size_t)MKV*2*D];      // cross-attn fused KV [2048 x 1536]
__device__ float g_x1 [MQ*D];
__device__ float g_x2 [MQ*D];
__device__ float g_ctx[MKV*D];                // tf32-rounded context
__device__ float g_ffh[(size_t)MQ*FFD];
__device__ float g_wts[3*DD];                 // repacked self QKV weights [2304 x 768] k-major
__device__ float g_wtc[3*DD];                 // repacked cross QKV weights
__device__ float g_w1t[(size_t)FFD*D];        // W1^T : [FF, D]
__device__ float g_w2t[(size_t)D*FFD];        // W2^T : [D, FF]
__device__ float g_bqkv[3*D];                 // concat self bias
__device__ float g_bkvc[2*D];                 // concat cross k,v bias

// ---------------- helpers ----------------
__device__ __forceinline__ uint32_t smem_u32(const void* p) {
    uint32_t a;
    asm("{ .reg .u64 t; cvta.to.shared.u64 t, %1; cvt.u32.u64 %0, t; }" : "=r"(a) : "l"(p));
    return a;
}
__device__ __forceinline__ float f2tf_f(float f) {
    uint32_t r; asm("cvt.rna.tf32.f32 %0, %1;" : "=r"(r) : "f"(f));
    return __uint_as_float(r);
}
__device__ __forceinline__ uint32_t f2tf_u(float f) {
    uint32_t r; asm("cvt.rna.tf32.f32 %0, %1;" : "=r"(r) : "f"(f));
    return r;
}
__device__ __forceinline__ void cp_async16(uint32_t dst, const void* src) {
    asm volatile("cp.async.cg.shared.global [%0], [%1], 16;" :: "r"(dst), "l"(src));
}
__device__ __forceinline__ void cp_commit() { asm volatile("cp.async.commit_group;"); }
template<int N> __device__ __forceinline__ void cp_wait() {
    asm volatile("cp.async.wait_group %0;" :: "n"(N));
}
__device__ __forceinline__ void mma_tf32(float* c, const uint32_t* a, const uint32_t* b) {
    asm volatile("mma.sync.aligned.m16n8k8.row.col.f32.tf32.tf32.f32 "
        "{%0,%1,%2,%3}, {%4,%5,%6,%7}, {%8,%9}, {%0,%1,%2,%3};"
        : "+f"(c[0]), "+f"(c[1]), "+f"(c[2]), "+f"(c[3])
        : "r"(a[0]), "r"(a[1]), "r"(a[2]), "r"(a[3]), "r"(b[0]), "r"(b[1]));
}
__device__ __forceinline__ float silu_f(float z) { return z / (1.0f + expf(-z)); }

// ---------------- LayerNorm (tf32-rounded output; feeds GEMM A) ----------------
__global__ void ln_kernel(const float* __restrict__ x, const float* __restrict__ w,
                          const float* __restrict__ b, float* __restrict__ out) {
    int row = blockIdx.x;
    const float* xr = x + (size_t)row * D;
    int tid = threadIdx.x;
    float v0 = xr[tid], v1 = xr[tid + 256], v2 = xr[tid + 512];
    float s  = v0 + v1 + v2;
    float sq = v0*v0 + v1*v1 + v2*v2;

    __shared__ float red[34];
    #pragma unroll
    for (int o = 16; o; o >>= 1) {
        s  += __shfl_down_sync(0xffffffffu, s,  o);
        sq += __shfl_down_sync(0xffffffffu, sq, o);
    }
    int wid = tid >> 5, lid = tid & 31;
    if (lid == 0) { red[wid] = s; red[8 + wid] = sq; }
    __syncthreads();
    if (tid < 8) {
        s = red[tid]; sq = red[8 + tid];
        #pragma unroll
        for (int o = 4; o; o >>= 1) {
            s  += __shfl_down_sync(0xffu, s,  o);
            sq += __shfl_down_sync(0xffu, sq, o);
        }
        if (tid == 0) {
            float mu  = s * (1.0f / D);
            float var = sq * (1.0f / D) - mu * mu;
            red[32] = mu;
            red[33] = rsqrtf(var + 1e-5f);
        }
    }
    __syncthreads();
    float mu = red[32], inv = red[33];
    float* orow = out + (size_t)row * D;
    orow[tid      ] = f2tf_f((v0 - mu) * inv * w[tid      ] + b[tid      ]);
    orow[tid + 256] = f2tf_f((v1 - mu) * inv * w[tid + 256] + b[tid + 256]);
    orow[tid + 512] = f2tf_f((v2 - mu) * inv * w[tid + 512] + b[tid + 512]);
}

// ------------- repack [H,D,HS] QKV weights -> [N=D rows, K=D] k-major, tf32 -------------
__global__ void repack_kernel(const float* __restrict__ Wq, const float* __restrict__ Wk,
                              const float* __restrict__ Wv, float* __restrict__ dst) {
    int i = blockIdx.x * blockDim.x + threadIdx.x;
    if (i >= 3 * DD) return;
    int m = i / DD;
    int r = i - m * DD;
    int n = r / D, k = r - n * D;
    const float* W = (m == 0) ? Wq : ((m == 1) ? Wk : Wv);
    dst[(size_t)m * DD + (size_t)n * D + k] =
        f2tf_f(W[(size_t)(n >> 6) * (D * HS) + (size_t)k * HS + (n & 63)]);
}

// ------------- tiled transpose + tf32 round -------------
__global__ void transpose_kernel(const float* __restrict__ src, float* __restrict__ dst,
                                 int R, int C) {
    __shared__ float tile[32][33];
    int bx = blockIdx.x * 32, by = blockIdx.y * 32;
    int x = bx + threadIdx.x;
    #pragma unroll
    for (int i = 0; i < 32; i += 8)
        tile[threadIdx.y + i][threadIdx.x] = src[(size_t)(by + threadIdx.y + i) * C + x];
    __syncthreads();
    int x2 = by + threadIdx.x;
    #pragma unroll
    for (int i = 0; i < 32; i += 8)
        dst[(size_t)(bx + threadIdx.y + i) * R + x2] = f2tf_f(tile[threadIdx.x][threadIdx.y + i]);
}

// ------------- elementwise tf32 round / bias concat -------------
__global__ void round_kernel(const float* __restrict__ src, float* __restrict__ dst, int n) {
    int i = blockIdx.x * blockDim.x + threadIdx.x;
    if (i < n) dst[i] = f2tf_f(src[i]);
}
__global__ void concat3_kernel(const float* __restrict__ a, const float* __restrict__ b,
                               const float* __restrict__ c, float* __restrict__ dst) {
    int i = blockIdx.x * blockDim.x + threadIdx.x;
    if (i < D) dst[i] = a[i];
    else if (i < 2 * D) dst[i] = b[i - D];
    else if (i < 3 * D) dst[i] = c[i - 2 * D];
}
__global__ void concat2_kernel(const float* __restrict__ a, const float* __restrict__ b,
                               float* __restrict__ dst) {
    int i = blockIdx.x * blockDim.x + threadIdx.x;
    if (i < D) dst[i] = a[i];
    else if (i < 2 * D) dst[i] = b[i - D];
}

// =======================================================================================
// tf32 mma.sync GEMM: C[M,N] = A[M,K] * Bt[N,K]^T + bias (+SiLU)(+res)(+tf32 round)
// =======================================================================================
#define BKk    32
#define RSTR   36
#define STAGES 4
#define TILEW  (128 * RSTR)

template<int ACT, bool RES, bool TFOUT>
__global__ __launch_bounds__(256)
void gemm_mma(const float* __restrict__ A, const float* __restrict__ Bt,
              const float* __restrict__ bias, const float* __restrict__ res,
              float* __restrict__ C, int M, int N, int K) {
    extern __shared__ float sm[];
    float* As = sm;
    float* Bs = sm + STAGES * TILEW;

    const int tid  = threadIdx.x;
    const int lane = tid & 31, wid = tid >> 5;
    const int warp_m = wid & 1, warp_n = wid >> 1;
    const int bm = blockIdx.y * 128, bn = blockIdx.x * 128;

    const int lrow = tid >> 3;
    const int lch  = tid & 7;
    const uint32_t sbase = smem_u32(sm);

    const float* Ag = A + (size_t)(bm + lrow) * K + lch * 4;
    const float* Bg = Bt + (size_t)(bn + lrow) * K + lch * 4;

    const int nt = K >> 5;

    auto prefetch = [&](int kt) {
        int s = kt % STAGES;
        uint32_t adst = sbase + (uint32_t)(s * TILEW + lrow * RSTR + lch * 4) * 4u;
        uint32_t bdst = sbase + (uint32_t)((STAGES + s) * TILEW + lrow * RSTR + lch * 4) * 4u;
        const float* ag = Ag + kt * BKk;
        const float* bg = Bg + kt * BKk;
        #pragma unroll
        for (int i = 0; i < 4; i++) {
            cp_async16(adst + (uint32_t)(i * 32 * RSTR) * 4u, ag + (size_t)(i * 32) * K);
            cp_async16(bdst + (uint32_t)(i * 32 * RSTR) * 4u, bg + (size_t)(i * 32) * K);
        }
    };

    float acc[4][4][4];
    #pragma unroll
    for (int mi = 0; mi < 4; mi++)
        #pragma unroll
        for (int ni = 0; ni < 4; ni++)
            #pragma unroll
            for (int e = 0; e < 4; e++) acc[mi][ni][e] = 0.0f;

    #pragma unroll
    for (int s = 0; s < STAGES - 1; s++) { prefetch(s); cp_commit(); }

    const int lr = lane >> 2, lc = lane & 3;
    const int am0 = warp_m * 64 + lr;
    const int bn0 = warp_n * 32 + lr;

    for (int kt = 0; kt < nt; kt++) {
        cp_wait<STAGES - 2>();
        __syncthreads();

        int s = kt % STAGES;
        const uint32_t* Asx = (const uint32_t*)(As + s * TILEW);
        const uint32_t* Bsx = (const uint32_t*)(Bs + s * TILEW);

        #pragma unroll
        for (int ks = 0; ks < 4; ks++) {
            int k0 = ks * 8;
            uint32_t af[4][4], bf[4][2];
            #pragma unroll
            for (int mi = 0; mi < 4; mi++) {
                int r = am0 + mi * 16;
                af[mi][0] = Asx[r * RSTR + k0 + lc];
                af[mi][1] = Asx[(r + 8) * RSTR + k0 + lc];
                af[mi][2] = Asx[r * RSTR + k0 + lc + 4];
                af[mi][3] = Asx[(r + 8) * RSTR + k0 + lc + 4];
            }
            #pragma unroll
            for (int ni = 0; ni < 4; ni++) {
                int n = bn0 + ni * 8;
                bf[ni][0] = Bsx[n * RSTR + k0 + lc];
                bf[ni][1] = Bsx[n * RSTR + k0 + lc + 4];
            }
            #pragma unroll
            for (int mi = 0; mi < 4; mi++)
                #pragma unroll
                for (int ni = 0; ni < 4; ni++)
                    mma_tf32(acc[mi][ni], af[mi], bf[ni]);
        }

        __syncthreads();
        if (kt + STAGES - 1 < nt) prefetch(kt + STAGES - 1);
        cp_commit();
    }

    #pragma unroll
    for (int mi = 0; mi < 4; mi++) {
        int r0 = bm + warp_m * 64 + mi * 16 + lr;
        #pragma unroll
        for (int ni = 0; ni < 4; ni++) {
            int c0 = bn + warp_n * 32 + ni * 8 + 2 * lc;
            float b0 = bias[c0], b1 = bias[c0 + 1];
            float v00 = acc[mi][ni][0] + b0, v01 = acc[mi][ni][1] + b1;
            float v10 = acc[mi][ni][2] + b0, v11 = acc[mi][ni][3] + b1;
            if (ACT == 1) { v00 = silu_f(v00); v01 = silu_f(v01); v10 = silu_f(v10); v11 = silu_f(v11); }
            if (RES) {
                const float2 rA = *(const float2*)(res + (size_t)r0 * N + c0);
                const float2 rB = *(const float2*)(res + (size_t)(r0 + 8) * N + c0);
                v00 += rA.x; v01 += rA.y; v10 += rB.x; v11 += rB.y;
            }
            if (TFOUT) { v00 = f2tf_f(v00); v01 = f2tf_f(v01); v10 = f2tf_f(v10); v11 = f2tf_f(v11); }
            *(float2*)(C + (size_t)r0 * N + c0)       = make_float2(v00, v01);
            *(float2*)(C + (size_t)(r0 + 8) * N + c0) = make_float2(v10, v11);
        }
    }
}

// =======================================================================================
// tensor-core flash attention (tf32 mma.sync), fused residual.
// grid: (Tq/128, H, B), 256 threads (8 warps, 16 q-rows each). K/V tiles of 64 keys,
// double-buffered cp.async. Q/K/V must be tf32-rounded fp32.
// =======================================================================================
#define KSTR 68   // K tile row stride (floats): lane -> 4*lr+lc, conflict-free
#define VSTR 72   // V tile row stride: 8*lc+lr, conflict-free
#define KTILE (64 * KSTR)
#define VTILE (64 * VSTR)

__global__ __launch_bounds__(256)
void attn_tc(const float* __restrict__ Q, int ldq,
             const float* __restrict__ Kg, const float* __restrict__ Vg, int ldkv,
             const float* __restrict__ xres, float* __restrict__ out,
             int Tq, int Tkv) {
    extern __shared__ float sm[];
    float* Ks = sm;                 // [2][64][KSTR]
    float* Vs = sm + 2 * KTILE;     // [2][64][VSTR]

    const int tid = threadIdx.x;
    const int lane = tid & 31, wid = tid >> 5;
    const int lr = lane >> 2, lc = lane & 3;
    const int h = blockIdx.y, b = blockIdx.z;
    const int brow = b * Tq + blockIdx.x * 128;
    const int m0 = wid * 16;

    const uint32_t sbase = smem_u32(sm);
    const float* Kb = Kg + (size_t)b * Tkv * ldkv + h * HS;
    const float* Vb = Vg + (size_t)b * Tkv * ldkv + h * HS;

    // ---- Q fragments in registers, pre-scaled by HS^-0.5 * log2(e) ----
    const float SC2 = 0.125f * 1.4426950408889634f;
    uint32_t qf[8][4];
    {
        const float* Qp = Q + (size_t)(brow + m0) * ldq + h * HS;
        #pragma unroll
        for (int ks = 0; ks < 8; ks++) {
            int c = ks * 8 + lc;
            qf[ks][0] = f2tf_u(__ldg(Qp + (size_t)lr * ldq + c) * SC2);
            qf[ks][1] = f2tf_u(__ldg(Qp + (size_t)(lr + 8) * ldq + c) * SC2);
            qf[ks][2] = f2tf_u(__ldg(Qp + (size_t)lr * ldq + c + 4) * SC2);
            qf[ks][3] = f2tf_u(__ldg(Qp + (size_t)(lr + 8) * ldq + c + 4) * SC2);
        }
    }

    // ---- KV tile prefetch (cp.async) ----
    auto prefetch = [&](int kt) {
        int buf = kt & 1;
        uint32_t kdst = sbase + (uint32_t)(buf * KTILE) * 4u;
        uint32_t vdst = sbase + (uint32_t)(2 * KTILE + buf * VTILE) * 4u;
        #pragma unroll
        for (int j = 0; j < 4; j++) {
            int chunk = tid + j * 256;        // 0..1023
            int r = chunk >> 4, c4 = chunk & 15;
            cp_async16(kdst + (uint32_t)(r * KSTR + c4 * 4) * 4u,
                       Kb + (size_t)(kt * 64 + r) * ldkv + c4 * 4);
            cp_async16(vdst + (uint32_t)(r * VSTR + c4 * 4) * 4u,
                       Vb + (size_t)(kt * 64 + r) * ldkv + c4 * 4);
        }
    };

    float oacc[8][4];
    #pragma unroll
    for (int i = 0; i < 8; i++)
        #pragma unroll
        for (int e = 0; e < 4; e++) oacc[i][e] = 0.0f;
    float mstate0 = -1e30f, mstate1 = -1e30f, l0 = 0.0f, l1 = 0.0f;

    const int nt = Tkv >> 6;
    prefetch(0); cp_commit();

    for (int kt = 0; kt < nt; kt++) {
        if (kt + 1 < nt) { prefetch(kt + 1); cp_commit(); cp_wait<1>(); }
        else             { cp_wait<0>(); }
        __syncthreads();

        const uint32_t* Ksb = (const uint32_t*)(Ks + (kt & 1) * KTILE);
        const uint32_t* Vsb = (const uint32_t*)(Vs + (kt & 1) * VTILE);

        // ---- S = Q K^T (already log2-scaled) ----
        float sacc[8][4];
        #pragma unroll
        for (int nf = 0; nf < 8; nf++)
            #pragma unroll
            for (int e = 0; e < 4; e++) sacc[nf][e] = 0.0f;

        #pragma unroll
        for (int nf = 0; nf < 8; nf++) {
            int n = nf * 8 + lr;
            #pragma unroll
            for (int ks = 0; ks < 8; ks++) {
                uint32_t bfr[2];
                bfr[0] = Ksb[n * KSTR + ks * 8 + lc];
                bfr[1] = Ksb[n * KSTR + ks * 8 + lc + 4];
                mma_tf32(sacc[nf], qf[ks], bfr);
            }
        }

        // ---- online softmax on fragments ----
        float mx0 = -1e30f, mx1 = -1e30f;
        #pragma unroll
        for (int nf = 0; nf < 8; nf++) {
            mx0 = fmaxf(mx0, fmaxf(sacc[nf][0], sacc[nf][1]));
            mx1 = fmaxf(mx1, fmaxf(sacc[nf][2], sacc[nf][3]));
        }
        mx0 = fmaxf(mx0, __shfl_xor_sync(0xffffffffu, mx0, 1));
        mx0 = fmaxf(mx0, __shfl_xor_sync(0xffffffffu, mx0, 2));
        mx1 = fmaxf(mx1, __shfl_xor_sync(0xffffffffu, mx1, 1));
        mx1 = fmaxf(mx1, __shfl_xor_sync(0xffffffffu, mx1, 2));
        float mn0 = fmaxf(mstate0, mx0), mn1 = fmaxf(mstate1, mx1);
        float corr0 = exp2f(mstate0 - mn0), corr1 = exp2f(mstate1 - mn1);
        mstate0 = mn0; mstate1 = mn1;

        float sum0 = 0.0f, sum1 = 0.0f;
        #pragma unroll
        for (int nf = 0; nf < 8; nf++) {
            sacc[nf][0] = exp2f(sacc[nf][0] - mn0);
            sacc[nf][1] = exp2f(sacc[nf][1] - mn0);
            sacc[nf][2] = exp2f(sacc[nf][2] - mn1);
            sacc[nf][3] = exp2f(sacc[nf][3] - mn1);
            sum0 += sacc[nf][0] + sacc[nf][1];
            sum1 += sacc[nf][2] + sacc[nf][3];
        }
        sum0 += __shfl_xor_sync(0xffffffffu, sum0, 1);
        sum0 += __shfl_xor_sync(0xffffffffu, sum0, 2);
        sum1 += __shfl_xor_sync(0xffffffffu, sum1, 1);
        sum1 += __shfl_xor_sync(0xffffffffu, sum1, 2);
        l0 = l0 * corr0 + sum0;
        l1 = l1 * corr1 + sum1;
        #pragma unroll
        for (int nf = 0; nf < 8; nf++) {
            oacc[nf][0] *= corr0; oacc[nf][1] *= corr0;
            oacc[nf][2] *= corr1; oacc[nf][3] *= corr1;
        }

        // ---- P·V : convert C-frags -> A-frags via intra-quad shuffles ----
        const int s0 = (lane & ~3) | (lc >> 1);
        const int s1 = s0 + 2;
        const bool odd = lc & 1;
        #pragma unroll
        for (int kg = 0; kg < 8; kg++) {
            float p0 = sacc[kg][0], p1 = sacc[kg][1], p2 = sacc[kg][2], p3 = sacc[kg][3];
            float e0 = __shfl_sync(0xffffffffu, p0, s0);
            float o0 = __shfl_sync(0xffffffffu, p1, s0);
            float e1 = __shfl_sync(0xffffffffu, p2, s0);
            float o1 = __shfl_sync(0xffffffffu, p3, s0);
            float e2 = __shfl_sync(0xffffffffu, p0, s1);
            float o2 = __shfl_sync(0xffffffffu, p1, s1);
            float e3 = __shfl_sync(0xffffffffu, p2, s1);
            float o3 = __shfl_sync(0xffffffffu, p3, s1);
            uint32_t af[4];
            af[0] = f2tf_u(odd ? o0 : e0);
            af[1] = f2tf_u(odd ? o1 : e1);
            af[2] = f2tf_u(odd ? o2 : e2);
            af[3] = f2tf_u(odd ? o3 : e3);
            #pragma unroll
            for (int nf2 = 0; nf2 < 8; nf2++) {
                uint32_t bfr[2];
                bfr[0] = Vsb[(kg * 8 + lc) * VSTR + nf2 * 8 + lr];
                bfr[1] = Vsb[(kg * 8 + lc + 4) * VSTR + nf2 * 8 + lr];
                mma_tf32(oacc[nf2], af, bfr);
            }
        }
        __syncthreads();
    }

    // ---- epilogue: normalize, add residual, store ----
    float inv0 = 1.0f / l0, inv1 = 1.0f / l1;
    int row0 = brow + m0 + lr, row1 = row0 + 8;
    #pragma unroll
    for (int nf2 = 0; nf2 < 8; nf2++) {
        int col = h * HS + nf2 * 8 + 2 * lc;
        float2 rA = *(const float2*)(xres + (size_t)row0 * D + col);
        float2 rB = *(const float2*)(xres + (size_t)row1 * D + col);
        *(float2*)(out + (size_t)row0 * D + col) =
            make_float2(rA.x + oacc[nf2][0] * inv0, rA.y + oacc[nf2][1] * inv0);
        *(float2*)(out + (size_t)row1 * D + col) =
            make_float2(rB.x + oacc[nf2][2] * inv1, rB.y + oacc[nf2][3] * inv1);
    }
}

// ---------------- host launch ----------------
extern "C" void kernel_launch(void* const* d_in, const int* in_sizes, int n_in,
                              void* d_out, int out_size) {
    const float* x0    = (const float*)d_in[0];
    const float* ctx   = (const float*)d_in[1];
    const float* ln1_w = (const float*)d_in[2];
    const float* ln1_b = (const float*)d_in[3];
    const float* sWq   = (const float*)d_in[4];
    const float* sbq   = (const float*)d_in[5];
    const float* sWk   = (const float*)d_in[6];
    const float* sbk   = (const float*)d_in[7];
    const float* sWv   = (const float*)d_in[8];
    const float* sbv   = (const float*)d_in[9];
    const float* ln2_w = (const float*)d_in[10];
    const float* ln2_b = (const float*)d_in[11];
    const float* cWq   = (const float*)d_in[12];
    const float* cbq   = (const float*)d_in[13];
    const float* cWk   = (const float*)d_in[14];
    const float* cbk   = (const float*)d_in[15];
    const float* cWv   = (const float*)d_in[16];
    const float* cbv   = (const float*)d_in[17];
    const float* ln3_w = (const float*)d_in[18];
    const float* ln3_b = (const float*)d_in[19];
    const float* W1    = (const float*)d_in[20];
    const float* b1    = (const float*)d_in[21];
    const float* W2    = (const float*)d_in[22];
    const float* b2    = (const float*)d_in[23];
    float* outp = (float*)d_out;

    float *ln, *q, *qkv, *kvc, *x1, *x2, *ctr, *ffh, *wts, *wtc, *w1t, *w2t, *bqkv, *bkvc;
    cudaGetSymbolAddress((void**)&ln,   g_ln);
    cudaGetSymbolAddress((void**)&q,    g_q);
    cudaGetSymbolAddress((void**)&qkv,  g_qkv);
    cudaGetSymbolAddress((void**)&kvc,  g_kvc);
    cudaGetSymbolAddress((void**)&x1,   g_x1);
    cudaGetSymbolAddress((void**)&x2,   g_x2);
    cudaGetSymbolAddress((void**)&ctr,  g_ctx);
    cudaGetSymbolAddress((void**)&ffh,  g_ffh);
    cudaGetSymbolAddress((void**)&wts,  g_wts);
    cudaGetSymbolAddress((void**)&wtc,  g_wtc);
    cudaGetSymbolAddress((void**)&w1t,  g_w1t);
    cudaGetSymbolAddress((void**)&w2t,  g_w2t);
    cudaGetSymbolAddress((void**)&bqkv, g_bqkv);
    cudaGetSymbolAddress((void**)&bkvc, g_bkvc);

    const int SMEM_GEMM = STAGES * TILEW * 2 * 4;            // 147456 B
    const int SMEM_ATTN = 2 * (KTILE + VTILE) * 4;           // 71680 B
    cudaFuncSetAttribute(gemm_mma<0, false, true >, cudaFuncAttributeMaxDynamicSharedMemorySize, SMEM_GEMM);
    cudaFuncSetAttribute(gemm_mma<1, false, true >, cudaFuncAttributeMaxDynamicSharedMemorySize, SMEM_GEMM);
    cudaFuncSetAttribute(gemm_mma<0, true,  false>, cudaFuncAttributeMaxDynamicSharedMemorySize, SMEM_GEMM);
    cudaFuncSetAttribute(attn_tc, cudaFuncAttributeMaxDynamicSharedMemorySize, SMEM_ATTN);

    dim3 gqkv (3 * D / 128, MQ / 128);   // (18, 64)
    dim3 gq   (D / 128, MQ / 128);       // (6, 64)
    dim3 gkvc (2 * D / 128, MKV / 128);  // (12, 16)
    dim3 gff1 (FFD / 128, MQ / 128);     // (24, 64)
    dim3 gff2 (D / 128, MQ / 128);       // (6, 64)

    // weight / input preprocessing
    repack_kernel<<<(3 * DD + 255) / 256, 256>>>(sWq, sWk, sWv, wts);
    repack_kernel<<<(3 * DD + 255) / 256, 256>>>(cWq, cWk, cWv, wtc);
    transpose_kernel<<<dim3(FFD / 32, D / 32), dim3(32, 8)>>>(W1, w1t, D, FFD);
    transpose_kernel<<<dim3(D / 32, FFD / 32), dim3(32, 8)>>>(W2, w2t, FFD, D);
    round_kernel<<<(MKV * D + 255) / 256, 256>>>(ctx, ctr, MKV * D);
    concat3_kernel<<<9, 256>>>(sbq, sbk, sbv, bqkv);
    concat2_kernel<<<6, 256>>>(cbk, cbv, bkvc);

    // ---- block 1: self attention (fused QKV) ----
    ln_kernel<<<MQ, 256>>>(x0, ln1_w, ln1_b, ln);
    gemm_mma<0, false, true><<<gqkv, 256, SMEM_GEMM>>>(ln, wts, bqkv, nullptr, qkv, MQ, 3 * D, D);
    attn_tc<<<dim3(TT / 128, HH, BB), 256, SMEM_ATTN>>>(qkv, 3 * D, qkv + D, qkv + 2 * D, 3 * D,
                                                        x0, x1, TT, TT);

    // ---- block 2: cross attention ----
    ln_kernel<<<MQ, 256>>>(x1, ln2_w, ln2_b, ln);
    gemm_mma<0, false, true><<<gq,   256, SMEM_GEMM>>>(ln,  wtc, cbq, nullptr, q,   MQ,  D,     D);
    gemm_mma<0, false, true><<<gkvc, 256, SMEM_GEMM>>>(ctr, wtc + DD, bkvc, nullptr, kvc, MKV, 2 * D, D);
    attn_tc<<<dim3(TT / 128, HH, BB), 256, SMEM_ATTN>>>(q, D, kvc, kvc + D, 2 * D,
                                                        x1, x2, TT, TCC);

    // ---- block 3: FFN ----
    ln_kernel<<<MQ, 256>>>(x2, ln3_w, ln3_b, ln);
    gemm_mma<1, false, true ><<<gff1, 256, SMEM_GEMM>>>(ln,  w1t, b1, nullptr, ffh,  MQ, FFD, D);
    gemm_mma<0, true,  false><<<gff2, 256, SMEM_GEMM>>>(ffh, w2t, b2, x2,      outp, MQ, D, FFD);
}

// round 5
// speedup vs baseline: 6.0452x; 1.7064x over previous
#include <cuda_runtime.h>
#include <cuda_fp16.h>
#include <math.h>
#include <stdint.h>

#define D   768
#define HH  12
#define HS  64
#define BB  8
#define TT  1024
#define TCC 256
#define FFD 3072
#define MQ  (BB*TT)    // 8192 rows
#define MKV (BB*TCC)   // 2048 rows
#define DD  (D*D)

// ---------------- scratch (device globals; no allocs allowed) ----------------
__device__ __half g_ln [MQ*D];
__device__ __half g_q  [MQ*D];                 // cross-attn Q
__device__ __half g_qkv[(size_t)MQ*3*D];       // self-attn fused QKV [8192 x 2304]
__device__ __half g_kvc[(size_t)MKV*2*D];      // cross-attn fused KV [2048 x 1536]
__device__ float  g_x1 [MQ*D];
__device__ float  g_x2 [MQ*D];
__device__ __half g_ctx[MKV*D];                // fp16 context
__device__ __half g_ffh[(size_t)MQ*FFD];
__device__ __half g_wts[3*DD];                 // repacked self QKV weights [2304 x 768] k-major
__device__ __half g_wtc[3*DD];                 // repacked cross QKV weights
__device__ __half g_w1t[(size_t)FFD*D];        // W1^T : [FF, D]
__device__ __half g_w2t[(size_t)D*FFD];        // W2^T : [D, FF]
__device__ float  g_bqkv[3*D];
__device__ float  g_bkvc[2*D];

// ---------------- helpers ----------------
__device__ __forceinline__ uint32_t smem_u32(const void* p) {
    uint32_t a;
    asm("{ .reg .u64 t; cvta.to.shared.u64 t, %1; cvt.u32.u64 %0, t; }" : "=r"(a) : "l"(p));
    return a;
}
__device__ __forceinline__ void cp_async16(uint32_t dst, const void* src) {
    asm volatile("cp.async.cg.shared.global [%0], [%1], 16;" :: "r"(dst), "l"(src));
}
__device__ __forceinline__ void cp_commit() { asm volatile("cp.async.commit_group;"); }
template<int N> __device__ __forceinline__ void cp_wait() {
    asm volatile("cp.async.wait_group %0;" :: "n"(N));
}
__device__ __forceinline__ void mma_f16(float* c, const uint32_t* a, const uint32_t* b) {
    asm volatile("mma.sync.aligned.m16n8k16.row.col.f32.f16.f16.f32 "
        "{%0,%1,%2,%3}, {%4,%5,%6,%7}, {%8,%9}, {%0,%1,%2,%3};"
        : "+f"(c[0]), "+f"(c[1]), "+f"(c[2]), "+f"(c[3])
        : "r"(a[0]), "r"(a[1]), "r"(a[2]), "r"(a[3]), "r"(b[0]), "r"(b[1]));
}
__device__ __forceinline__ void ldm_x4(uint32_t& r0, uint32_t& r1, uint32_t& r2, uint32_t& r3, uint32_t a) {
    asm volatile("ldmatrix.sync.aligned.m8n8.x4.shared.b16 {%0,%1,%2,%3}, [%4];"
        : "=r"(r0), "=r"(r1), "=r"(r2), "=r"(r3) : "r"(a));
}
__device__ __forceinline__ void ldm_x4t(uint32_t& r0, uint32_t& r1, uint32_t& r2, uint32_t& r3, uint32_t a) {
    asm volatile("ldmatrix.sync.aligned.m8n8.x4.trans.shared.b16 {%0,%1,%2,%3}, [%4];"
        : "=r"(r0), "=r"(r1), "=r"(r2), "=r"(r3) : "r"(a));
}
__device__ __forceinline__ uint32_t packh2(float x, float y) {
    __half2 h = __floats2half2_rn(x, y);
    return *(uint32_t*)&h;
}
__device__ __forceinline__ float silu_f(float z) { return z / (1.0f + expf(-z)); }

// ---------------- LayerNorm (fp16 output; feeds GEMM A) ----------------
__global__ void ln_kernel(const float* __restrict__ x, const float* __restrict__ w,
                          const float* __restrict__ b, __half* __restrict__ out) {
    int row = blockIdx.x;
    const float* xr = x + (size_t)row * D;
    int tid = threadIdx.x;
    float v0 = xr[tid], v1 = xr[tid + 256], v2 = xr[tid + 512];
    float s  = v0 + v1 + v2;
    float sq = v0*v0 + v1*v1 + v2*v2;

    __shared__ float red[34];
    #pragma unroll
    for (int o = 16; o; o >>= 1) {
        s  += __shfl_down_sync(0xffffffffu, s,  o);
        sq += __shfl_down_sync(0xffffffffu, sq, o);
    }
    int wid = tid >> 5, lid = tid & 31;
    if (lid == 0) { red[wid] = s; red[8 + wid] = sq; }
    __syncthreads();
    if (tid < 8) {
        s = red[tid]; sq = red[8 + tid];
        #pragma unroll
        for (int o = 4; o; o >>= 1) {
            s  += __shfl_down_sync(0xffu, s,  o);
            sq += __shfl_down_sync(0xffu, sq, o);
        }
        if (tid == 0) {
            float mu  = s * (1.0f / D);
            float var = sq * (1.0f / D) - mu * mu;
            red[32] = mu;
            red[33] = rsqrtf(var + 1e-5f);
        }
    }
    __syncthreads();
    float mu = red[32], inv = red[33];
    __half* orow = out + (size_t)row * D;
    orow[tid      ] = __float2half_rn((v0 - mu) * inv * w[tid      ] + b[tid      ]);
    orow[tid + 256] = __float2half_rn((v1 - mu) * inv * w[tid + 256] + b[tid + 256]);
    orow[tid + 512] = __float2half_rn((v2 - mu) * inv * w[tid + 512] + b[tid + 512]);
}

// ------------- repack [H,D,HS] QKV weights -> [N rows, K] k-major fp16 -------------
__global__ void repack_kernel(const float* __restrict__ Wq, const float* __restrict__ Wk,
                              const float* __restrict__ Wv, __half* __restrict__ dst) {
    int i = blockIdx.x * blockDim.x + threadIdx.x;
    if (i >= 3 * DD) return;
    int m = i / DD;
    int r = i - m * DD;
    int n = r / D, k = r - n * D;
    const float* W = (m == 0) ? Wq : ((m == 1) ? Wk : Wv);
    dst[(size_t)m * DD + (size_t)n * D + k] =
        __float2half_rn(W[(size_t)(n >> 6) * (D * HS) + (size_t)k * HS + (n & 63)]);
}

// ------------- tiled transpose + fp16 convert -------------
__global__ void transpose_kernel(const float* __restrict__ src, __half* __restrict__ dst,
                                 int R, int C) {
    __shared__ float tile[32][33];
    int bx = blockIdx.x * 32, by = blockIdx.y * 32;
    int x = bx + threadIdx.x;
    #pragma unroll
    for (int i = 0; i < 32; i += 8)
        tile[threadIdx.y + i][threadIdx.x] = src[(size_t)(by + threadIdx.y + i) * C + x];
    __syncthreads();
    int x2 = by + threadIdx.x;
    #pragma unroll
    for (int i = 0; i < 32; i += 8)
        dst[(size_t)(bx + threadIdx.y + i) * R + x2] = __float2half_rn(tile[threadIdx.x][threadIdx.y + i]);
}

__global__ void round_kernel(const float* __restrict__ src, __half* __restrict__ dst, int n) {
    int i = blockIdx.x * blockDim.x + threadIdx.x;
    if (i < n) dst[i] = __float2half_rn(src[i]);
}
__global__ void concat3_kernel(const float* __restrict__ a, const float* __restrict__ b,
                               const float* __restrict__ c, float* __restrict__ dst) {
    int i = blockIdx.x * blockDim.x + threadIdx.x;
    if (i < D) dst[i] = a[i];
    else if (i < 2 * D) dst[i] = b[i - D];
    else if (i < 3 * D) dst[i] = c[i - 2 * D];
}
__global__ void concat2_kernel(const float* __restrict__ a, const float* __restrict__ b,
                               float* __restrict__ dst) {
    int i = blockIdx.x * blockDim.x + threadIdx.x;
    if (i < D) dst[i] = a[i];
    else if (i < 2 * D) dst[i] = b[i - D];
}

// =======================================================================================
// fp16 mma.sync GEMM: C[M,N] = A[M,K] * Bt[N,K]^T + bias (+SiLU)(+res), fp32 accum.
// BM=BN=128, BK=32 halfs, 256 threads (8 warps x 64x32), 4-stage cp.async.
// Smem word stride 20/row (conflict-free fragment LDS).
// =======================================================================================
#define WS     20                  // words (=half2) per smem row
#define STAGES 4
#define TILEWW (128 * WS)          // words per stage per operand (2560)

template<int ACT, bool RES, bool OUTH>
__global__ __launch_bounds__(256)
void gemm_mma(const __half* __restrict__ A, const __half* __restrict__ Bt,
              const float* __restrict__ bias, const float* __restrict__ res,
              void* __restrict__ Cv, int M, int N, int K) {
    extern __shared__ uint32_t smw[];

    const int tid  = threadIdx.x;
    const int lane = tid & 31, wid = tid >> 5;
    const int warp_m = wid & 1, warp_n = wid >> 1;
    const int bm = blockIdx.y * 128, bn = blockIdx.x * 128;
    const uint32_t sbase = smem_u32(smw);

    const int r0l = tid >> 2, subl = tid & 3;
    const __half* Ag = A + (size_t)(bm + r0l) * K + subl * 8;
    const __half* Bg = Bt + (size_t)(bn + r0l) * K + subl * 8;
    const uint32_t adst0 = sbase + (uint32_t)(r0l * WS + subl * 4) * 4u;
    const uint32_t bdst0 = sbase + (uint32_t)(STAGES * TILEWW + r0l * WS + subl * 4) * 4u;

    const int nt = K >> 5;

    auto prefetch = [&](int kt) {
        int s = kt % STAGES;
        uint32_t ad = adst0 + (uint32_t)(s * TILEWW) * 4u;
        uint32_t bd = bdst0 + (uint32_t)(s * TILEWW) * 4u;
        const __half* ag = Ag + kt * 32;
        const __half* bg = Bg + kt * 32;
        cp_async16(ad, ag);
        cp_async16(ad + (uint32_t)(64 * WS) * 4u, ag + (size_t)64 * K);
        cp_async16(bd, bg);
        cp_async16(bd + (uint32_t)(64 * WS) * 4u, bg + (size_t)64 * K);
    };

    float acc[4][4][4];
    #pragma unroll
    for (int mi = 0; mi < 4; mi++)
        #pragma unroll
        for (int ni = 0; ni < 4; ni++)
            #pragma unroll
            for (int e = 0; e < 4; e++) acc[mi][ni][e] = 0.0f;

    #pragma unroll
    for (int s = 0; s < STAGES - 1; s++) { prefetch(s); cp_commit(); }

    const int lr = lane >> 2, lc = lane & 3;
    const int am0 = warp_m * 64 + lr;
    const int bn0 = warp_n * 32 + lr;

    for (int kt = 0; kt < nt; kt++) {
        cp_wait<STAGES - 2>();
        __syncthreads();
        if (kt + STAGES - 1 < nt) prefetch(kt + STAGES - 1);
        cp_commit();

        int s = kt % STAGES;
        const uint32_t* Asx = smw + s * TILEWW;
        const uint32_t* Bsx = smw + (STAGES + s) * TILEWW;

        #pragma unroll
        for (int ks = 0; ks < 2; ks++) {
            int k0 = ks * 8;
            uint32_t af[4][4], bf[4][2];
            #pragma unroll
            for (int mi = 0; mi < 4; mi++) {
                int r = am0 + mi * 16;
                af[mi][0] = Asx[r * WS + k0 + lc];
                af[mi][1] = Asx[(r + 8) * WS + k0 + lc];
                af[mi][2] = Asx[r * WS + k0 + lc + 4];
                af[mi][3] = Asx[(r + 8) * WS + k0 + lc + 4];
            }
            #pragma unroll
            for (int ni = 0; ni < 4; ni++) {
                int n = bn0 + ni * 8;
                bf[ni][0] = Bsx[n * WS + k0 + lc];
                bf[ni][1] = Bsx[n * WS + k0 + lc + 4];
            }
            #pragma unroll
            for (int mi = 0; mi < 4; mi++)
                #pragma unroll
                for (int ni = 0; ni < 4; ni++)
                    mma_f16(acc[mi][ni], af[mi], bf[ni]);
        }
    }

    // ---- epilogue: fused bias / SiLU / residual ----
    #pragma unroll
    for (int mi = 0; mi < 4; mi++) {
        int r0 = bm + warp_m * 64 + mi * 16 + lr;
        #pragma unroll
        for (int ni = 0; ni < 4; ni++) {
            int c0 = bn + warp_n * 32 + ni * 8 + 2 * lc;
            float b0 = bias[c0], b1 = bias[c0 + 1];
            float v00 = acc[mi][ni][0] + b0, v01 = acc[mi][ni][1] + b1;
            float v10 = acc[mi][ni][2] + b0, v11 = acc[mi][ni][3] + b1;
            if (ACT == 1) { v00 = silu_f(v00); v01 = silu_f(v01); v10 = silu_f(v10); v11 = silu_f(v11); }
            if (RES) {
                const float2 rA = *(const float2*)(res + (size_t)r0 * N + c0);
                const float2 rB = *(const float2*)(res + (size_t)(r0 + 8) * N + c0);
                v00 += rA.x; v01 += rA.y; v10 += rB.x; v11 += rB.y;
            }
            if (OUTH) {
                __half* Ch = (__half*)Cv;
                uint32_t p0 = packh2(v00, v01), p1 = packh2(v10, v11);
                *(uint32_t*)(Ch + (size_t)r0 * N + c0)       = p0;
                *(uint32_t*)(Ch + (size_t)(r0 + 8) * N + c0) = p1;
            } else {
                float* Cf = (float*)Cv;
                *(float2*)(Cf + (size_t)r0 * N + c0)       = make_float2(v00, v01);
                *(float2*)(Cf + (size_t)(r0 + 8) * N + c0) = make_float2(v10, v11);
            }
        }
    }
}

// =======================================================================================
// fp16 tensor-core flash attention, fused residual. 256 threads, 8 warps x 16 q-rows.
// 64-key K/V tiles, double-buffered cp.async. K via ldmatrix, V via ldmatrix.trans.
// Row stride 72 halfs (144 B) -> conflict-free.
// =======================================================================================
#define KVSTR_B 144                       // bytes per row
#define KTILE_B (64 * KVSTR_B)            // 9216 B per tile

__global__ __launch_bounds__(256)
void attn_tc(const __half* __restrict__ Q, int ldq,
             const __half* __restrict__ Kg, const __half* __restrict__ Vg, int ldkv,
             const float* __restrict__ xres, float* __restrict__ out,
             int Tq, int Tkv) {
    extern __shared__ uint32_t smw[];
    const uint32_t sbase = smem_u32(smw);

    const int tid = threadIdx.x;
    const int lane = tid & 31, wid = tid >> 5;
    const int lr = lane >> 2, lc = lane & 3;
    const int h = blockIdx.y, b = blockIdx.z;
    const int brow = b * Tq + blockIdx.x * 128;
    const int m0 = wid * 16;

    const __half* Kb = Kg + (size_t)b * Tkv * ldkv + h * HS;
    const __half* Vb = Vg + (size_t)b * Tkv * ldkv + h * HS;

    // ---- Q fragments, pre-scaled by HS^-0.5 * log2(e) ----
    const float SC2 = 0.125f * 1.4426950408889634f;
    uint32_t qf[4][4];
    {
        const __half* Qp = Q + (size_t)(brow + m0) * ldq + h * HS;
        #pragma unroll
        for (int ks = 0; ks < 4; ks++) {
            int c = ks * 16 + 2 * lc;
            #pragma unroll
            for (int e = 0; e < 4; e++) {
                int rr = (e & 1) ? lr + 8 : lr;
                int cc = c + ((e >> 1) ? 8 : 0);
                __half2 hv = *(const __half2*)(Qp + (size_t)rr * ldq + cc);
                float2 f = __half22float2(hv);
                qf[ks][e] = packh2(f.x * SC2, f.y * SC2);
            }
        }
    }

    // ldmatrix lane offsets
    const int rl = lane & 7;
    const uint32_t loff_k = (uint32_t)(rl * KVSTR_B + ((lane >> 3) * 16));
    const uint32_t loff_v = (uint32_t)(((((lane >> 3) & 1) * 8 + rl) * KVSTR_B) + ((lane >> 4) * 16));

    const int lrow = tid >> 3, lsub = tid & 7;     // KV loader: 32 rows/pass
    auto prefetch = [&](int kt) {
        int buf = kt & 1;
        uint32_t kdst = sbase + buf * KTILE_B + lrow * KVSTR_B + lsub * 16;
        uint32_t vdst = kdst + 2 * KTILE_B;
        const __half* kp = Kb + (size_t)(kt * 64 + lrow) * ldkv + lsub * 8;
        const __half* vp = Vb + (size_t)(kt * 64 + lrow) * ldkv + lsub * 8;
        cp_async16(kdst, kp);
        cp_async16(kdst + 32 * KVSTR_B, kp + (size_t)32 * ldkv);
        cp_async16(vdst, vp);
        cp_async16(vdst + 32 * KVSTR_B, vp + (size_t)32 * ldkv);
    };

    float oacc[8][4];
    #pragma unroll
    for (int i = 0; i < 8; i++)
        #pragma unroll
        for (int e = 0; e < 4; e++) oacc[i][e] = 0.0f;
    float mstate0 = -1e30f, mstate1 = -1e30f, l0 = 0.0f, l1 = 0.0f;

    const int nt = Tkv >> 6;
    prefetch(0); cp_commit();

    for (int kt = 0; kt < nt; kt++) {
        if (kt + 1 < nt) { prefetch(kt + 1); cp_commit(); cp_wait<1>(); }
        else             { cp_wait<0>(); }
        __syncthreads();

        const uint32_t kbase = sbase + (kt & 1) * KTILE_B;
        const uint32_t vbase = kbase + 2 * KTILE_B;

        // ---- S = Q K^T ----
        float sacc[8][4];
        #pragma unroll
        for (int nf = 0; nf < 8; nf++)
            #pragma unroll
            for (int e = 0; e < 4; e++) sacc[nf][e] = 0.0f;

        #pragma unroll
        for (int nf = 0; nf < 8; nf++) {
            uint32_t k0, k1, k2, k3, k4, k5, k6, k7;
            uint32_t base = kbase + nf * (8 * KVSTR_B) + loff_k;
            ldm_x4(k0, k1, k2, k3, base);
            ldm_x4(k4, k5, k6, k7, base + 64);
            uint32_t bf[2];
            bf[0] = k0; bf[1] = k1; mma_f16(sacc[nf], qf[0], bf);
            bf[0] = k2; bf[1] = k3; mma_f16(sacc[nf], qf[1], bf);
            bf[0] = k4; bf[1] = k5; mma_f16(sacc[nf], qf[2], bf);
            bf[0] = k6; bf[1] = k7; mma_f16(sacc[nf], qf[3], bf);
        }

        // ---- online softmax (base-2) ----
        float mx0 = -1e30f, mx1 = -1e30f;
        #pragma unroll
        for (int nf = 0; nf < 8; nf++) {
            mx0 = fmaxf(mx0, fmaxf(sacc[nf][0], sacc[nf][1]));
            mx1 = fmaxf(mx1, fmaxf(sacc[nf][2], sacc[nf][3]));
        }
        mx0 = fmaxf(mx0, __shfl_xor_sync(0xffffffffu, mx0, 1));
        mx0 = fmaxf(mx0, __shfl_xor_sync(0xffffffffu, mx0, 2));
        mx1 = fmaxf(mx1, __shfl_xor_sync(0xffffffffu, mx1, 1));
        mx1 = fmaxf(mx1, __shfl_xor_sync(0xffffffffu, mx1, 2));
        float mn0 = fmaxf(mstate0, mx0), mn1 = fmaxf(mstate1, mx1);
        float corr0 = exp2f(mstate0 - mn0), corr1 = exp2f(mstate1 - mn1);
        mstate0 = mn0; mstate1 = mn1;

        float sum0 = 0.0f, sum1 = 0.0f;
        #pragma unroll
        for (int nf = 0; nf < 8; nf++) {
            sacc[nf][0] = exp2f(sacc[nf][0] - mn0);
            sacc[nf][1] = exp2f(sacc[nf][1] - mn0);
            sacc[nf][2] = exp2f(sacc[nf][2] - mn1);
            sacc[nf][3] = exp2f(sacc[nf][3] - mn1);
            sum0 += sacc[nf][0] + sacc[nf][1];
            sum1 += sacc[nf][2] + sacc[nf][3];
        }
        sum0 += __shfl_xor_sync(0xffffffffu, sum0, 1);
        sum0 += __shfl_xor_sync(0xffffffffu, sum0, 2);
        sum1 += __shfl_xor_sync(0xffffffffu, sum1, 1);
        sum1 += __shfl_xor_sync(0xffffffffu, sum1, 2);
        l0 = l0 * corr0 + sum0;
        l1 = l1 * corr1 + sum1;
        #pragma unroll
        for (int nf = 0; nf < 8; nf++) {
            oacc[nf][0] *= corr0; oacc[nf][1] *= corr0;
            oacc[nf][2] *= corr1; oacc[nf][3] *= corr1;
        }

        // ---- P·V : C-frag of S == A-frag for fp16 PV (no shuffles) ----
        #pragma unroll
        for (int kg = 0; kg < 4; kg++) {
            uint32_t af[4];
            af[0] = packh2(sacc[2*kg][0],   sacc[2*kg][1]);
            af[1] = packh2(sacc[2*kg][2],   sacc[2*kg][3]);
            af[2] = packh2(sacc[2*kg+1][0], sacc[2*kg+1][1]);
            af[3] = packh2(sacc[2*kg+1][2], sacc[2*kg+1][3]);
            #pragma unroll
            for (int nfp = 0; nfp < 4; nfp++) {
                uint32_t v0, v1, v2, v3;
                ldm_x4t(v0, v1, v2, v3, vbase + kg * (16 * KVSTR_B) + nfp * 32 + loff_v);
                uint32_t bf[2];
                bf[0] = v0; bf[1] = v1; mma_f16(oacc[2*nfp],     af, bf);
                bf[0] = v2; bf[1] = v3; mma_f16(oacc[2*nfp + 1], af, bf);
            }
        }
        __syncthreads();
    }

    // ---- epilogue: normalize, add residual, store fp32 ----
    float inv0 = 1.0f / l0, inv1 = 1.0f / l1;
    int row0 = brow + m0 + lr, row1 = row0 + 8;
    #pragma unroll
    for (int nf = 0; nf < 8; nf++) {
        int col = h * HS + nf * 8 + 2 * lc;
        float2 rA = *(const float2*)(xres + (size_t)row0 * D + col);
        float2 rB = *(const float2*)(xres + (size_t)row1 * D + col);
        *(float2*)(out + (size_t)row0 * D + col) =
            make_float2(rA.x + oacc[nf][0] * inv0, rA.y + oacc[nf][1] * inv0);
        *(float2*)(out + (size_t)row1 * D + col) =
            make_float2(rB.x + oacc[nf][2] * inv1, rB.y + oacc[nf][3] * inv1);
    }
}

// ---------------- host launch ----------------
extern "C" void kernel_launch(void* const* d_in, const int* in_sizes, int n_in,
                              void* d_out, int out_size) {
    const float* x0    = (const float*)d_in[0];
    const float* ctx   = (const float*)d_in[1];
    const float* ln1_w = (const float*)d_in[2];
    const float* ln1_b = (const float*)d_in[3];
    const float* sWq   = (const float*)d_in[4];
    const float* sbq   = (const float*)d_in[5];
    const float* sWk   = (const float*)d_in[6];
    const float* sbk   = (const float*)d_in[7];
    const float* sWv   = (const float*)d_in[8];
    const float* sbv   = (const float*)d_in[9];
    const float* ln2_w = (const float*)d_in[10];
    const float* ln2_b = (const float*)d_in[11];
    const float* cWq   = (const float*)d_in[12];
    const float* cbq   = (const float*)d_in[13];
    const float* cWk   = (const float*)d_in[14];
    const float* cbk   = (const float*)d_in[15];
    const float* cWv   = (const float*)d_in[16];
    const float* cbv   = (const float*)d_in[17];
    const float* ln3_w = (const float*)d_in[18];
    const float* ln3_b = (const float*)d_in[19];
    const float* W1    = (const float*)d_in[20];
    const float* b1    = (const float*)d_in[21];
    const float* W2    = (const float*)d_in[22];
    const float* b2    = (const float*)d_in[23];
    float* outp = (float*)d_out;

    __half *ln, *q, *qkv, *kvc, *ctr, *ffh, *wts, *wtc, *w1t, *w2t;
    float *x1, *x2, *bqkv, *bkvc;
    cudaGetSymbolAddress((void**)&ln,   g_ln);
    cudaGetSymbolAddress((void**)&q,    g_q);
    cudaGetSymbolAddress((void**)&qkv,  g_qkv);
    cudaGetSymbolAddress((void**)&kvc,  g_kvc);
    cudaGetSymbolAddress((void**)&x1,   g_x1);
    cudaGetSymbolAddress((void**)&x2,   g_x2);
    cudaGetSymbolAddress((void**)&ctr,  g_ctx);
    cudaGetSymbolAddress((void**)&ffh,  g_ffh);
    cudaGetSymbolAddress((void**)&wts,  g_wts);
    cudaGetSymbolAddress((void**)&wtc,  g_wtc);
    cudaGetSymbolAddress((void**)&w1t,  g_w1t);
    cudaGetSymbolAddress((void**)&w2t,  g_w2t);
    cudaGetSymbolAddress((void**)&bqkv, g_bqkv);
    cudaGetSymbolAddress((void**)&bkvc, g_bkvc);

    const int SMEM_GEMM = STAGES * TILEWW * 2 * 4;   // 81920 B
    const int SMEM_ATTN = 4 * KTILE_B;               // 36864 B
    cudaFuncSetAttribute(gemm_mma<0, false, true >, cudaFuncAttributeMaxDynamicSharedMemorySize, SMEM_GEMM);
    cudaFuncSetAttribute(gemm_mma<1, false, true >, cudaFuncAttributeMaxDynamicSharedMemorySize, SMEM_GEMM);
    cudaFuncSetAttribute(gemm_mma<0, true,  false>, cudaFuncAttributeMaxDynamicSharedMemorySize, SMEM_GEMM);
    cudaFuncSetAttribute(attn_tc, cudaFuncAttributeMaxDynamicSharedMemorySize, SMEM_ATTN);

    dim3 gqkv (3 * D / 128, MQ / 128);   // (18, 64)
    dim3 gq   (D / 128, MQ / 128);       // (6, 64)
    dim3 gkvc (2 * D / 128, MKV / 128);  // (12, 16)
    dim3 gff1 (FFD / 128, MQ / 128);     // (24, 64)
    dim3 gff2 (D / 128, MQ / 128);       // (6, 64)

    // preprocessing
    repack_kernel<<<(3 * DD + 255) / 256, 256>>>(sWq, sWk, sWv, wts);
    repack_kernel<<<(3 * DD + 255) / 256, 256>>>(cWq, cWk, cWv, wtc);
    transpose_kernel<<<dim3(FFD / 32, D / 32), dim3(32, 8)>>>(W1, w1t, D, FFD);
    transpose_kernel<<<dim3(D / 32, FFD / 32), dim3(32, 8)>>>(W2, w2t, FFD, D);
    round_kernel<<<(MKV * D + 255) / 256, 256>>>(ctx, ctr, MKV * D);
    concat3_kernel<<<9, 256>>>(sbq, sbk, sbv, bqkv);
    concat2_kernel<<<6, 256>>>(cbk, cbv, bkvc);

    // ---- block 1: self attention (fused QKV) ----
    ln_kernel<<<MQ, 256>>>(x0, ln1_w, ln1_b, ln);
    gemm_mma<0, false, true><<<gqkv, 256, SMEM_GEMM>>>(ln, wts, bqkv, nullptr, qkv, MQ, 3 * D, D);
    attn_tc<<<dim3(TT / 128, HH, BB), 256, SMEM_ATTN>>>(qkv, 3 * D, qkv + D, qkv + 2 * D, 3 * D,
                                                        x0, x1, TT, TT);

    // ---- block 2: cross attention ----
    ln_kernel<<<MQ, 256>>>(x1, ln2_w, ln2_b, ln);
    gemm_mma<0, false, true><<<gq,   256, SMEM_GEMM>>>(ln,  wtc, cbq, nullptr, q,   MQ,  D,     D);
    gemm_mma<0, false, true><<<gkvc, 256, SMEM_GEMM>>>(ctr, wtc + DD, bkvc, nullptr, kvc, MKV, 2 * D, D);
    attn_tc<<<dim3(TT / 128, HH, BB), 256, SMEM_ATTN>>>(q, D, kvc, kvc + D, 2 * D,
                                                        x1, x2, TT, TCC);

    // ---- block 3: FFN ----
    ln_kernel<<<MQ, 256>>>(x2, ln3_w, ln3_b, ln);
    gemm_mma<1, false, true ><<<gff1, 256, SMEM_GEMM>>>(ln,  w1t, b1, nullptr, ffh,  MQ, FFD, D);
    gemm_mma<0, true,  false><<<gff2, 256, SMEM_GEMM>>>(ffh, w2t, b2, x2,      outp, MQ, D, FFD);
}

// round 6
// speedup vs baseline: 7.0802x; 1.1712x over previous
#include <cuda_runtime.h>
#include <cuda_fp16.h>
#include <math.h>
#include <stdint.h>

#define D   768
#define HH  12
#define HS  64
#define BB  8
#define TT  1024
#define TCC 256
#define FFD 3072
#define MQ  (BB*TT)    // 8192 rows
#define MKV (BB*TCC)   // 2048 rows
#define DD  (D*D)

// ---------------- scratch (device globals; no allocs allowed) ----------------
__device__ __half g_ln [MQ*D];
__device__ __half g_q  [MQ*D];                 // cross-attn Q
__device__ __half g_qkv[(size_t)MQ*3*D];       // self-attn fused QKV [8192 x 2304]
__device__ __half g_kvc[(size_t)MKV*2*D];      // cross-attn fused KV [2048 x 1536]
__device__ float  g_x1 [MQ*D];
__device__ float  g_x2 [MQ*D];
__device__ __half g_ctx[MKV*D];                // fp16 context
__device__ __half g_ffh[(size_t)MQ*FFD];
__device__ __half g_wts[3*DD];                 // repacked self QKV weights [2304 x 768] k-major
__device__ __half g_wtc[3*DD];                 // repacked cross QKV weights
__device__ __half g_w1t[(size_t)FFD*D];        // W1^T : [FF, D]
__device__ __half g_w2t[(size_t)D*FFD];        // W2^T : [D, FF]
__device__ float  g_bqkv[3*D];
__device__ float  g_bkvc[2*D];

// ---------------- helpers ----------------
__device__ __forceinline__ uint32_t smem_u32(const void* p) {
    uint32_t a;
    asm("{ .reg .u64 t; cvta.to.shared.u64 t, %1; cvt.u32.u64 %0, t; }" : "=r"(a) : "l"(p));
    return a;
}
__device__ __forceinline__ void cp_async16(uint32_t dst, const void* src) {
    asm volatile("cp.async.cg.shared.global [%0], [%1], 16;" :: "r"(dst), "l"(src));
}
__device__ __forceinline__ void cp_commit() { asm volatile("cp.async.commit_group;"); }
template<int N> __device__ __forceinline__ void cp_wait() {
    asm volatile("cp.async.wait_group %0;" :: "n"(N));
}
__device__ __forceinline__ void mma_f16(float* c, const uint32_t* a, const uint32_t* b) {
    asm volatile("mma.sync.aligned.m16n8k16.row.col.f32.f16.f16.f32 "
        "{%0,%1,%2,%3}, {%4,%5,%6,%7}, {%8,%9}, {%0,%1,%2,%3};"
        : "+f"(c[0]), "+f"(c[1]), "+f"(c[2]), "+f"(c[3])
        : "r"(a[0]), "r"(a[1]), "r"(a[2]), "r"(a[3]), "r"(b[0]), "r"(b[1]));
}
__device__ __forceinline__ void ldm_x4(uint32_t& r0, uint32_t& r1, uint32_t& r2, uint32_t& r3, uint32_t a) {
    asm volatile("ldmatrix.sync.aligned.m8n8.x4.shared.b16 {%0,%1,%2,%3}, [%4];"
        : "=r"(r0), "=r"(r1), "=r"(r2), "=r"(r3) : "r"(a));
}
__device__ __forceinline__ void ldm_x4t(uint32_t& r0, uint32_t& r1, uint32_t& r2, uint32_t& r3, uint32_t a) {
    asm volatile("ldmatrix.sync.aligned.m8n8.x4.trans.shared.b16 {%0,%1,%2,%3}, [%4];"
        : "=r"(r0), "=r"(r1), "=r"(r2), "=r"(r3) : "r"(a));
}
__device__ __forceinline__ uint32_t packh2(float x, float y) {
    __half2 h = __floats2half2_rn(x, y);
    return *(uint32_t*)&h;
}
__device__ __forceinline__ float silu_f(float z) { return z / (1.0f + expf(-z)); }

// ---------------- LayerNorm (fp16 output; feeds GEMM A) ----------------
__global__ void ln_kernel(const float* __restrict__ x, const float* __restrict__ w,
                          const float* __restrict__ b, __half* __restrict__ out) {
    int row = blockIdx.x;
    const float* xr = x + (size_t)row * D;
    int tid = threadIdx.x;
    float v0 = xr[tid], v1 = xr[tid + 256], v2 = xr[tid + 512];
    float s  = v0 + v1 + v2;
    float sq = v0*v0 + v1*v1 + v2*v2;

    __shared__ float red[34];
    #pragma unroll
    for (int o = 16; o; o >>= 1) {
        s  += __shfl_down_sync(0xffffffffu, s,  o);
        sq += __shfl_down_sync(0xffffffffu, sq, o);
    }
    int wid = tid >> 5, lid = tid & 31;
    if (lid == 0) { red[wid] = s; red[8 + wid] = sq; }
    __syncthreads();
    if (tid < 8) {
        s = red[tid]; sq = red[8 + tid];
        #pragma unroll
        for (int o = 4; o; o >>= 1) {
            s  += __shfl_down_sync(0xffu, s,  o);
            sq += __shfl_down_sync(0xffu, sq, o);
        }
        if (tid == 0) {
            float mu  = s * (1.0f / D);
            float var = sq * (1.0f / D) - mu * mu;
            red[32] = mu;
            red[33] = rsqrtf(var + 1e-5f);
        }
    }
    __syncthreads();
    float mu = red[32], inv = red[33];
    __half* orow = out + (size_t)row * D;
    orow[tid      ] = __float2half_rn((v0 - mu) * inv * w[tid      ] + b[tid      ]);
    orow[tid + 256] = __float2half_rn((v1 - mu) * inv * w[tid + 256] + b[tid + 256]);
    orow[tid + 512] = __float2half_rn((v2 - mu) * inv * w[tid + 512] + b[tid + 512]);
}

// ------------- repack [H,D,HS] QKV weights -> [N rows, K] k-major fp16 -------------
__global__ void repack_kernel(const float* __restrict__ Wq, const float* __restrict__ Wk,
                              const float* __restrict__ Wv, __half* __restrict__ dst) {
    int i = blockIdx.x * blockDim.x + threadIdx.x;
    if (i >= 3 * DD) return;
    int m = i / DD;
    int r = i - m * DD;
    int n = r / D, k = r - n * D;
    const float* W = (m == 0) ? Wq : ((m == 1) ? Wk : Wv);
    dst[(size_t)m * DD + (size_t)n * D + k] =
        __float2half_rn(W[(size_t)(n >> 6) * (D * HS) + (size_t)k * HS + (n & 63)]);
}

// ------------- tiled transpose + fp16 convert -------------
__global__ void transpose_kernel(const float* __restrict__ src, __half* __restrict__ dst,
                                 int R, int C) {
    __shared__ float tile[32][33];
    int bx = blockIdx.x * 32, by = blockIdx.y * 32;
    int x = bx + threadIdx.x;
    #pragma unroll
    for (int i = 0; i < 32; i += 8)
        tile[threadIdx.y + i][threadIdx.x] = src[(size_t)(by + threadIdx.y + i) * C + x];
    __syncthreads();
    int x2 = by + threadIdx.x;
    #pragma unroll
    for (int i = 0; i < 32; i += 8)
        dst[(size_t)(bx + threadIdx.y + i) * R + x2] = __float2half_rn(tile[threadIdx.x][threadIdx.y + i]);
}

__global__ void round_kernel(const float* __restrict__ src, __half* __restrict__ dst, int n) {
    int i = blockIdx.x * blockDim.x + threadIdx.x;
    if (i < n) dst[i] = __float2half_rn(src[i]);
}
__global__ void concat3_kernel(const float* __restrict__ a, const float* __restrict__ b,
                               const float* __restrict__ c, float* __restrict__ dst) {
    int i = blockIdx.x * blockDim.x + threadIdx.x;
    if (i < D) dst[i] = a[i];
    else if (i < 2 * D) dst[i] = b[i - D];
    else if (i < 3 * D) dst[i] = c[i - 2 * D];
}
__global__ void concat2_kernel(const float* __restrict__ a, const float* __restrict__ b,
                               float* __restrict__ dst) {
    int i = blockIdx.x * blockDim.x + threadIdx.x;
    if (i < D) dst[i] = a[i];
    else if (i < 2 * D) dst[i] = b[i - D];
}

// =======================================================================================
// fp16 mma.sync GEMM: C[M,N] = A[M,K] * Bt[N,K]^T + bias (+SiLU)(+res), fp32 accum.
// BM=BN=128, BK=32 halfs, 256 threads (8 warps x 64x32), 4-stage cp.async,
// fragments loaded with ldmatrix.x4. Smem word stride 20/row (conflict-free).
// =======================================================================================
#define WS     20                  // words per smem row
#define STAGES 4
#define TILEWW (128 * WS)          // words per stage per operand (2560)

template<int ACT, bool RES, bool OUTH>
__global__ __launch_bounds__(256)
void gemm_mma(const __half* __restrict__ A, const __half* __restrict__ Bt,
              const float* __restrict__ bias, const float* __restrict__ res,
              void* __restrict__ Cv, int M, int N, int K) {
    extern __shared__ uint32_t smw[];

    const int tid  = threadIdx.x;
    const int lane = tid & 31, wid = tid >> 5;
    const int warp_m = wid & 1, warp_n = wid >> 1;
    const int bm = blockIdx.y * 128, bn = blockIdx.x * 128;
    const uint32_t sbase = smem_u32(smw);

    const int r0l = tid >> 2, subl = tid & 3;
    const __half* Ag = A + (size_t)(bm + r0l) * K + subl * 8;
    const __half* Bg = Bt + (size_t)(bn + r0l) * K + subl * 8;
    const uint32_t adst0 = sbase + (uint32_t)(r0l * WS + subl * 4) * 4u;
    const uint32_t bdst0 = sbase + (uint32_t)(STAGES * TILEWW + r0l * WS + subl * 4) * 4u;

    const int nt = K >> 5;

    auto prefetch = [&](int kt) {
        int s = kt % STAGES;
        uint32_t ad = adst0 + (uint32_t)(s * TILEWW) * 4u;
        uint32_t bd = bdst0 + (uint32_t)(s * TILEWW) * 4u;
        const __half* ag = Ag + kt * 32;
        const __half* bg = Bg + kt * 32;
        cp_async16(ad, ag);
        cp_async16(ad + (uint32_t)(64 * WS) * 4u, ag + (size_t)64 * K);
        cp_async16(bd, bg);
        cp_async16(bd + (uint32_t)(64 * WS) * 4u, bg + (size_t)64 * K);
    };

    float acc[4][4][4];
    #pragma unroll
    for (int mi = 0; mi < 4; mi++)
        #pragma unroll
        for (int ni = 0; ni < 4; ni++)
            #pragma unroll
            for (int e = 0; e < 4; e++) acc[mi][ni][e] = 0.0f;

    #pragma unroll
    for (int s = 0; s < STAGES - 1; s++) { prefetch(s); cp_commit(); }

    // ldmatrix per-lane byte offsets (within a stage)
    // A x4 (per mi): rows warp_m*64 + mi*16 + (lane&15), col halfs (lane>>4)*8
    const uint32_t a_l = (uint32_t)((warp_m * 64 + (lane & 15)) * WS) * 4u + (uint32_t)((lane >> 4) * 16);
    // B x4 (per nip=2 ni): rows warp_n*32 + nip*16 + (lane&7) + ((lane>>4)*8), col halfs ((lane>>3)&1)*8
    const uint32_t b_l = (uint32_t)(STAGES * TILEWW) * 4u +
                         (uint32_t)((warp_n * 32 + (lane & 7) + ((lane >> 4) << 3)) * WS) * 4u +
                         (uint32_t)(((lane >> 3) & 1) * 16);

    for (int kt = 0; kt < nt; kt++) {
        cp_wait<STAGES - 2>();
        __syncthreads();
        if (kt + STAGES - 1 < nt) prefetch(kt + STAGES - 1);
        cp_commit();

        int s = kt % STAGES;
        const uint32_t soff = (uint32_t)(s * TILEWW) * 4u;
        const uint32_t abase_s = sbase + soff + a_l;
        const uint32_t bbase_s = sbase + soff + b_l;

        #pragma unroll
        for (int ks = 0; ks < 2; ks++) {
            const uint32_t koff = (uint32_t)(ks * 32);   // 8 words = 32 B
            uint32_t af[4][4], bf[4][2];
            #pragma unroll
            for (int mi = 0; mi < 4; mi++)
                ldm_x4(af[mi][0], af[mi][1], af[mi][2], af[mi][3],
                       abase_s + (uint32_t)(mi * 16 * WS) * 4u + koff);
            ldm_x4(bf[0][0], bf[0][1], bf[1][0], bf[1][1], bbase_s + koff);
            ldm_x4(bf[2][0], bf[2][1], bf[3][0], bf[3][1],
                   bbase_s + (uint32_t)(16 * WS) * 4u + koff);
            #pragma unroll
            for (int mi = 0; mi < 4; mi++)
                #pragma unroll
                for (int ni = 0; ni < 4; ni++)
                    mma_f16(acc[mi][ni], af[mi], bf[ni]);
        }
    }

    // ---- epilogue: fused bias / SiLU / residual ----
    const int lr = lane >> 2, lc = lane & 3;
    #pragma unroll
    for (int mi = 0; mi < 4; mi++) {
        int r0 = bm + warp_m * 64 + mi * 16 + lr;
        #pragma unroll
        for (int ni = 0; ni < 4; ni++) {
            int c0 = bn + warp_n * 32 + ni * 8 + 2 * lc;
            float b0 = bias[c0], b1 = bias[c0 + 1];
            float v00 = acc[mi][ni][0] + b0, v01 = acc[mi][ni][1] + b1;
            float v10 = acc[mi][ni][2] + b0, v11 = acc[mi][ni][3] + b1;
            if (ACT == 1) { v00 = silu_f(v00); v01 = silu_f(v01); v10 = silu_f(v10); v11 = silu_f(v11); }
            if (RES) {
                const float2 rA = *(const float2*)(res + (size_t)r0 * N + c0);
                const float2 rB = *(const float2*)(res + (size_t)(r0 + 8) * N + c0);
                v00 += rA.x; v01 += rA.y; v10 += rB.x; v11 += rB.y;
            }
            if (OUTH) {
                __half* Ch = (__half*)Cv;
                uint32_t p0 = packh2(v00, v01), p1 = packh2(v10, v11);
                *(uint32_t*)(Ch + (size_t)r0 * N + c0)       = p0;
                *(uint32_t*)(Ch + (size_t)(r0 + 8) * N + c0) = p1;
            } else {
                float* Cf = (float*)Cv;
                *(float2*)(Cf + (size_t)r0 * N + c0)       = make_float2(v00, v01);
                *(float2*)(Cf + (size_t)(r0 + 8) * N + c0) = make_float2(v10, v11);
            }
        }
    }
}

// =======================================================================================
// fp16 tensor-core flash attention, fused residual. 256 threads, 8 warps x 16 q-rows.
// 64-key K/V tiles, double-buffered cp.async. K via ldmatrix, V via ldmatrix.trans.
// Row stride 72 halfs (144 B) -> conflict-free.
// =======================================================================================
#define KVSTR_B 144                       // bytes per row
#define KTILE_B (64 * KVSTR_B)            // 9216 B per tile

__global__ __launch_bounds__(256)
void attn_tc(const __half* __restrict__ Q, int ldq,
             const __half* __restrict__ Kg, const __half* __restrict__ Vg, int ldkv,
             const float* __restrict__ xres, float* __restrict__ out,
             int Tq, int Tkv) {
    extern __shared__ uint32_t smw[];
    const uint32_t sbase = smem_u32(smw);

    const int tid = threadIdx.x;
    const int lane = tid & 31, wid = tid >> 5;
    const int lr = lane >> 2, lc = lane & 3;
    const int h = blockIdx.y, b = blockIdx.z;
    const int brow = b * Tq + blockIdx.x * 128;
    const int m0 = wid * 16;

    const __half* Kb = Kg + (size_t)b * Tkv * ldkv + h * HS;
    const __half* Vb = Vg + (size_t)b * Tkv * ldkv + h * HS;

    // ---- Q fragments, pre-scaled by HS^-0.5 * log2(e) ----
    const float SC2 = 0.125f * 1.4426950408889634f;
    uint32_t qf[4][4];
    {
        const __half* Qp = Q + (size_t)(brow + m0) * ldq + h * HS;
        #pragma unroll
        for (int ks = 0; ks < 4; ks++) {
            int c = ks * 16 + 2 * lc;
            #pragma unroll
            for (int e = 0; e < 4; e++) {
                int rr = (e & 1) ? lr + 8 : lr;
                int cc = c + ((e >> 1) ? 8 : 0);
                __half2 hv = *(const __half2*)(Qp + (size_t)rr * ldq + cc);
                float2 f = __half22float2(hv);
                qf[ks][e] = packh2(f.x * SC2, f.y * SC2);
            }
        }
    }

    const int rl = lane & 7;
    const uint32_t loff_k = (uint32_t)(rl * KVSTR_B + ((lane >> 3) * 16));
    const uint32_t loff_v = (uint32_t)(((((lane >> 3) & 1) * 8 + rl) * KVSTR_B) + ((lane >> 4) * 16));

    const int lrow = tid >> 3, lsub = tid & 7;
    auto prefetch = [&](int kt) {
        int buf = kt & 1;
        uint32_t kdst = sbase + buf * KTILE_B + lrow * KVSTR_B + lsub * 16;
        uint32_t vdst = kdst + 2 * KTILE_B;
        const __half* kp = Kb + (size_t)(kt * 64 + lrow) * ldkv + lsub * 8;
        const __half* vp = Vb + (size_t)(kt * 64 + lrow) * ldkv + lsub * 8;
        cp_async16(kdst, kp);
        cp_async16(kdst + 32 * KVSTR_B, kp + (size_t)32 * ldkv);
        cp_async16(vdst, vp);
        cp_async16(vdst + 32 * KVSTR_B, vp + (size_t)32 * ldkv);
    };

    float oacc[8][4];
    #pragma unroll
    for (int i = 0; i < 8; i++)
        #pragma unroll
        for (int e = 0; e < 4; e++) oacc[i][e] = 0.0f;
    float mstate0 = -1e30f, mstate1 = -1e30f, l0 = 0.0f, l1 = 0.0f;

    const int nt = Tkv >> 6;
    prefetch(0); cp_commit();

    for (int kt = 0; kt < nt; kt++) {
        if (kt + 1 < nt) { prefetch(kt + 1); cp_commit(); cp_wait<1>(); }
        else             { cp_wait<0>(); }
        __syncthreads();

        const uint32_t kbase = sbase + (kt & 1) * KTILE_B;
        const uint32_t vbase = kbase + 2 * KTILE_B;

        // ---- S = Q K^T ----
        float sacc[8][4];
        #pragma unroll
        for (int nf = 0; nf < 8; nf++)
            #pragma unroll
            for (int e = 0; e < 4; e++) sacc[nf][e] = 0.0f;

        #pragma unroll
        for (int nf = 0; nf < 8; nf++) {
            uint32_t k0, k1, k2, k3, k4, k5, k6, k7;
            uint32_t base = kbase + nf * (8 * KVSTR_B) + loff_k;
            ldm_x4(k0, k1, k2, k3, base);
            ldm_x4(k4, k5, k6, k7, base + 64);
            uint32_t bf[2];
            bf[0] = k0; bf[1] = k1; mma_f16(sacc[nf], qf[0], bf);
            bf[0] = k2; bf[1] = k3; mma_f16(sacc[nf], qf[1], bf);
            bf[0] = k4; bf[1] = k5; mma_f16(sacc[nf], qf[2], bf);
            bf[0] = k6; bf[1] = k7; mma_f16(sacc[nf], qf[3], bf);
        }

        // ---- online softmax (base-2) ----
        float mx0 = -1e30f, mx1 = -1e30f;
        #pragma unroll
        for (int nf = 0; nf < 8; nf++) {
            mx0 = fmaxf(mx0, fmaxf(sacc[nf][0], sacc[nf][1]));
            mx1 = fmaxf(mx1, fmaxf(sacc[nf][2], sacc[nf][3]));
        }
        mx0 = fmaxf(mx0, __shfl_xor_sync(0xffffffffu, mx0, 1));
        mx0 = fmaxf(mx0, __shfl_xor_sync(0xffffffffu, mx0, 2));
        mx1 = fmaxf(mx1, __shfl_xor_sync(0xffffffffu, mx1, 1));
        mx1 = fmaxf(mx1, __shfl_xor_sync(0xffffffffu, mx1, 2));
        float mn0 = fmaxf(mstate0, mx0), mn1 = fmaxf(mstate1, mx1);
        float corr0 = exp2f(mstate0 - mn0), corr1 = exp2f(mstate1 - mn1);
        mstate0 = mn0; mstate1 = mn1;

        float sum0 = 0.0f, sum1 = 0.0f;
        #pragma unroll
        for (int nf = 0; nf < 8; nf++) {
            sacc[nf][0] = exp2f(sacc[nf][0] - mn0);
            sacc[nf][1] = exp2f(sacc[nf][1] - mn0);
            sacc[nf][2] = exp2f(sacc[nf][2] - mn1);
            sacc[nf][3] = exp2f(sacc[nf][3] - mn1);
            sum0 += sacc[nf][0] + sacc[nf][1];
            sum1 += sacc[nf][2] + sacc[nf][3];
        }
        sum0 += __shfl_xor_sync(0xffffffffu, sum0, 1);
        sum0 += __shfl_xor_sync(0xffffffffu, sum0, 2);
        sum1 += __shfl_xor_sync(0xffffffffu, sum1, 1);
        sum1 += __shfl_xor_sync(0xffffffffu, sum1, 2);
        l0 = l0 * corr0 + sum0;
        l1 = l1 * corr1 + sum1;
        #pragma unroll
        for (int nf = 0; nf < 8; nf++) {
            oacc[nf][0] *= corr0; oacc[nf][1] *= corr0;
            oacc[nf][2] *= corr1; oacc[nf][3] *= corr1;
        }

        // ---- P·V ----
        #pragma unroll
        for (int kg = 0; kg < 4; kg++) {
            uint32_t af[4];
            af[0] = packh2(sacc[2*kg][0],   sacc[2*kg][1]);
            af[1] = packh2(sacc[2*kg][2],   sacc[2*kg][3]);
            af[2] = packh2(sacc[2*kg+1][0], sacc[2*kg+1][1]);
            af[3] = packh2(sacc[2*kg+1][2], sacc[2*kg+1][3]);
            #pragma unroll
            for (int nfp = 0; nfp < 4; nfp++) {
                uint32_t v0, v1, v2, v3;
                ldm_x4t(v0, v1, v2, v3, vbase + kg * (16 * KVSTR_B) + nfp * 32 + loff_v);
                uint32_t bf[2];
                bf[0] = v0; bf[1] = v1; mma_f16(oacc[2*nfp],     af, bf);
                bf[0] = v2; bf[1] = v3; mma_f16(oacc[2*nfp + 1], af, bf);
            }
        }
        __syncthreads();
    }

    // ---- epilogue: normalize, add residual, store fp32 ----
    float inv0 = 1.0f / l0, inv1 = 1.0f / l1;
    int row0 = brow + m0 + lr, row1 = row0 + 8;
    #pragma unroll
    for (int nf = 0; nf < 8; nf++) {
        int col = h * HS + nf * 8 + 2 * lc;
        float2 rA = *(const float2*)(xres + (size_t)row0 * D + col);
        float2 rB = *(const float2*)(xres + (size_t)row1 * D + col);
        *(float2*)(out + (size_t)row0 * D + col) =
            make_float2(rA.x + oacc[nf][0] * inv0, rA.y + oacc[nf][1] * inv0);
        *(float2*)(out + (size_t)row1 * D + col) =
            make_float2(rB.x + oacc[nf][2] * inv1, rB.y + oacc[nf][3] * inv1);
    }
}

// ---------------- host launch ----------------
extern "C" void kernel_launch(void* const* d_in, const int* in_sizes, int n_in,
                              void* d_out, int out_size) {
    const float* x0    = (const float*)d_in[0];
    const float* ctx   = (const float*)d_in[1];
    const float* ln1_w = (const float*)d_in[2];
    const float* ln1_b = (const float*)d_in[3];
    const float* sWq   = (const float*)d_in[4];
    const float* sbq   = (const float*)d_in[5];
    const float* sWk   = (const float*)d_in[6];
    const float* sbk   = (const float*)d_in[7];
    const float* sWv   = (const float*)d_in[8];
    const float* sbv   = (const float*)d_in[9];
    const float* ln2_w = (const float*)d_in[10];
    const float* ln2_b = (const float*)d_in[11];
    const float* cWq   = (const float*)d_in[12];
    const float* cbq   = (const float*)d_in[13];
    const float* cWk   = (const float*)d_in[14];
    const float* cbk   = (const float*)d_in[15];
    const float* cWv   = (const float*)d_in[16];
    const float* cbv   = (const float*)d_in[17];
    const float* ln3_w = (const float*)d_in[18];
    const float* ln3_b = (const float*)d_in[19];
    const float* W1    = (const float*)d_in[20];
    const float* b1    = (const float*)d_in[21];
    const float* W2    = (const float*)d_in[22];
    const float* b2    = (const float*)d_in[23];
    float* outp = (float*)d_out;

    __half *ln, *q, *qkv, *kvc, *ctr, *ffh, *wts, *wtc, *w1t, *w2t;
    float *x1, *x2, *bqkv, *bkvc;
    cudaGetSymbolAddress((void**)&ln,   g_ln);
    cudaGetSymbolAddress((void**)&q,    g_q);
    cudaGetSymbolAddress((void**)&qkv,  g_qkv);
    cudaGetSymbolAddress((void**)&kvc,  g_kvc);
    cudaGetSymbolAddress((void**)&x1,   g_x1);
    cudaGetSymbolAddress((void**)&x2,   g_x2);
    cudaGetSymbolAddress((void**)&ctr,  g_ctx);
    cudaGetSymbolAddress((void**)&ffh,  g_ffh);
    cudaGetSymbolAddress((void**)&wts,  g_wts);
    cudaGetSymbolAddress((void**)&wtc,  g_wtc);
    cudaGetSymbolAddress((void**)&w1t,  g_w1t);
    cudaGetSymbolAddress((void**)&w2t,  g_w2t);
    cudaGetSymbolAddress((void**)&bqkv, g_bqkv);
    cudaGetSymbolAddress((void**)&bkvc, g_bkvc);

    const int SMEM_GEMM = STAGES * TILEWW * 2 * 4;   // 81920 B
    const int SMEM_ATTN = 4 * KTILE_B;               // 36864 B
    cudaFuncSetAttribute(gemm_mma<0, false, true >, cudaFuncAttributeMaxDynamicSharedMemorySize, SMEM_GEMM);
    cudaFuncSetAttribute(gemm_mma<1, false, true >, cudaFuncAttributeMaxDynamicSharedMemorySize, SMEM_GEMM);
    cudaFuncSetAttribute(gemm_mma<0, true,  false>, cudaFuncAttributeMaxDynamicSharedMemorySize, SMEM_GEMM);
    cudaFuncSetAttribute(attn_tc, cudaFuncAttributeMaxDynamicSharedMemorySize, SMEM_ATTN);

    dim3 gqkv (3 * D / 128, MQ / 128);   // (18, 64)
    dim3 gq   (D / 128, MQ / 128);       // (6, 64)
    dim3 gkvc (2 * D / 128, MKV / 128);  // (12, 16)
    dim3 gff1 (FFD / 128, MQ / 128);     // (24, 64)
    dim3 gff2 (D / 128, MQ / 128);       // (6, 64)

    // preprocessing
    repack_kernel<<<(3 * DD + 255) / 256, 256>>>(sWq, sWk, sWv, wts);
    repack_kernel<<<(3 * DD + 255) / 256, 256>>>(cWq, cWk, cWv, wtc);
    transpose_kernel<<<dim3(FFD / 32, D / 32), dim3(32, 8)>>>(W1, w1t, D, FFD);
    transpose_kernel<<<dim3(D / 32, FFD / 32), dim3(32, 8)>>>(W2, w2t, FFD, D);
    round_kernel<<<(MKV * D + 255) / 256, 256>>>(ctx, ctr, MKV * D);
    concat3_kernel<<<9, 256>>>(sbq, sbk, sbv, bqkv);
    concat2_kernel<<<6, 256>>>(cbk, cbv, bkvc);

    // ---- block 1: self attention (fused QKV) ----
    ln_kernel<<<MQ, 256>>>(x0, ln1_w, ln1_b, ln);
    gemm_mma<0, false, true><<<gqkv, 256, SMEM_GEMM>>>(ln, wts, bqkv, nullptr, qkv, MQ, 3 * D, D);
    attn_tc<<<dim3(TT / 128, HH, BB), 256, SMEM_ATTN>>>(qkv, 3 * D, qkv + D, qkv + 2 * D, 3 * D,
                                                        x0, x1, TT, TT);

    // ---- block 2: cross attention ----
    ln_kernel<<<MQ, 256>>>(x1, ln2_w, ln2_b, ln);
    gemm_mma<0, false, true><<<gq,   256, SMEM_GEMM>>>(ln,  wtc, cbq, nullptr, q,   MQ,  D,     D);
    gemm_mma<0, false, true><<<gkvc, 256, SMEM_GEMM>>>(ctr, wtc + DD, bkvc, nullptr, kvc, MKV, 2 * D, D);
    attn_tc<<<dim3(TT / 128, HH, BB), 256, SMEM_ATTN>>>(q, D, kvc, kvc + D, 2 * D,
                                                        x1, x2, TT, TCC);

    // ---- block 3: FFN ----
    ln_kernel<<<MQ, 256>>>(x2, ln3_w, ln3_b, ln);
    gemm_mma<1, false, true ><<<gff1, 256, SMEM_GEMM>>>(ln,  w1t, b1, nullptr, ffh,  MQ, FFD, D);
    gemm_mma<0, true,  false><<<gff2, 256, SMEM_GEMM>>>(ffh, w2t, b2, x2,      outp, MQ, D, FFD);
}

// round 7
// speedup vs baseline: 7.5845x; 1.0712x over previous
#include <cuda_runtime.h>
#include <cuda_fp16.h>
#include <math.h>
#include <stdint.h>

#define D   768
#define HH  12
#define HS  64
#define BB  8
#define TT  1024
#define TCC 256
#define FFD 3072
#define MQ  (BB*TT)    // 8192 rows
#define MKV (BB*TCC)   // 2048 rows
#define DD  (D*D)

// ---------------- scratch (device globals; no allocs allowed) ----------------
__device__ __half g_ln [MQ*D];
__device__ __half g_q  [MQ*D];                 // cross-attn Q
__device__ __half g_qkv[(size_t)MQ*3*D];       // self-attn fused QKV [8192 x 2304]
__device__ __half g_kvc[(size_t)MKV*2*D];      // cross-attn fused KV [2048 x 1536]
__device__ float  g_x1 [MQ*D];
__device__ float  g_x2 [MQ*D];
__device__ __half g_ctx[MKV*D];                // fp16 context
__device__ __half g_ffh[(size_t)MQ*FFD];
__device__ __half g_wts[3*DD];                 // repacked self QKV weights [2304 x 768] k-major
__device__ __half g_wtc[3*DD];                 // repacked cross QKV weights
__device__ __half g_w1t[(size_t)FFD*D];        // W1^T : [FF, D]
__device__ __half g_w2t[(size_t)D*FFD];        // W2^T : [D, FF]
__device__ float  g_bqkv[3*D];
__device__ float  g_bkvc[2*D];

// ---------------- helpers ----------------
__device__ __forceinline__ uint32_t smem_u32(const void* p) {
    uint32_t a;
    asm("{ .reg .u64 t; cvta.to.shared.u64 t, %1; cvt.u32.u64 %0, t; }" : "=r"(a) : "l"(p));
    return a;
}
__device__ __forceinline__ void cp_async16(uint32_t dst, const void* src) {
    asm volatile("cp.async.cg.shared.global [%0], [%1], 16;" :: "r"(dst), "l"(src));
}
__device__ __forceinline__ void cp_commit() { asm volatile("cp.async.commit_group;"); }
template<int N> __device__ __forceinline__ void cp_wait() {
    asm volatile("cp.async.wait_group %0;" :: "n"(N));
}
__device__ __forceinline__ void mma_f16(float* c, const uint32_t* a, const uint32_t* b) {
    asm volatile("mma.sync.aligned.m16n8k16.row.col.f32.f16.f16.f32 "
        "{%0,%1,%2,%3}, {%4,%5,%6,%7}, {%8,%9}, {%0,%1,%2,%3};"
        : "+f"(c[0]), "+f"(c[1]), "+f"(c[2]), "+f"(c[3])
        : "r"(a[0]), "r"(a[1]), "r"(a[2]), "r"(a[3]), "r"(b[0]), "r"(b[1]));
}
__device__ __forceinline__ void ldm_x4(uint32_t& r0, uint32_t& r1, uint32_t& r2, uint32_t& r3, uint32_t a) {
    asm volatile("ldmatrix.sync.aligned.m8n8.x4.shared.b16 {%0,%1,%2,%3}, [%4];"
        : "=r"(r0), "=r"(r1), "=r"(r2), "=r"(r3) : "r"(a));
}
__device__ __forceinline__ void ldm_x4t(uint32_t& r0, uint32_t& r1, uint32_t& r2, uint32_t& r3, uint32_t a) {
    asm volatile("ldmatrix.sync.aligned.m8n8.x4.trans.shared.b16 {%0,%1,%2,%3}, [%4];"
        : "=r"(r0), "=r"(r1), "=r"(r2), "=r"(r3) : "r"(a));
}
__device__ __forceinline__ uint32_t packh2(float x, float y) {
    __half2 h = __floats2half2_rn(x, y);
    return *(uint32_t*)&h;
}
__device__ __forceinline__ float silu_f(float z) { return z / (1.0f + expf(-z)); }

// ---------------- LayerNorm: warp-per-row, no smem, fp16 out ----------------
// grid MQ/8, block 256 (8 warps = 8 rows). Each lane owns 24 elems (6 x float4).
__global__ void ln_kernel(const float* __restrict__ x, const float* __restrict__ w,
                          const float* __restrict__ b, __half* __restrict__ out) {
    int lane = threadIdx.x & 31, wrp = threadIdx.x >> 5;
    int row = blockIdx.x * 8 + wrp;
    const float* xr = x + (size_t)row * D;

    float4 v[6];
    float s = 0.0f, sq = 0.0f;
    #pragma unroll
    for (int j = 0; j < 6; j++) {
        v[j] = *(const float4*)(xr + lane * 4 + j * 128);
        s  += (v[j].x + v[j].y) + (v[j].z + v[j].w);
        sq += v[j].x*v[j].x + v[j].y*v[j].y + v[j].z*v[j].z + v[j].w*v[j].w;
    }
    #pragma unroll
    for (int o = 16; o; o >>= 1) {
        s  += __shfl_xor_sync(0xffffffffu, s,  o);
        sq += __shfl_xor_sync(0xffffffffu, sq, o);
    }
    float mu  = s * (1.0f / D);
    float inv = rsqrtf(sq * (1.0f / D) - mu * mu + 1e-5f);

    __half* orow = out + (size_t)row * D;
    #pragma unroll
    for (int j = 0; j < 6; j++) {
        int c = lane * 4 + j * 128;
        float4 wv = *(const float4*)(w + c);
        float4 bv = *(const float4*)(b + c);
        __half2 h0 = __floats2half2_rn((v[j].x - mu) * inv * wv.x + bv.x,
                                       (v[j].y - mu) * inv * wv.y + bv.y);
        __half2 h1 = __floats2half2_rn((v[j].z - mu) * inv * wv.z + bv.z,
                                       (v[j].w - mu) * inv * wv.w + bv.w);
        uint2 pk = make_uint2(*(uint32_t*)&h0, *(uint32_t*)&h1);
        *(uint2*)(orow + c) = pk;
    }
}

// ------------- repack [H,D,HS] QKV weights -> [N rows, K] k-major fp16 -------------
__global__ void repack_kernel(const float* __restrict__ Wq, const float* __restrict__ Wk,
                              const float* __restrict__ Wv, __half* __restrict__ dst) {
    int i = blockIdx.x * blockDim.x + threadIdx.x;
    if (i >= 3 * DD) return;
    int m = i / DD;
    int r = i - m * DD;
    int n = r / D, k = r - n * D;
    const float* W = (m == 0) ? Wq : ((m == 1) ? Wk : Wv);
    dst[(size_t)m * DD + (size_t)n * D + k] =
        __float2half_rn(W[(size_t)(n >> 6) * (D * HS) + (size_t)k * HS + (n & 63)]);
}

// ------------- tiled transpose + fp16 convert -------------
__global__ void transpose_kernel(const float* __restrict__ src, __half* __restrict__ dst,
                                 int R, int C) {
    __shared__ float tile[32][33];
    int bx = blockIdx.x * 32, by = blockIdx.y * 32;
    int x = bx + threadIdx.x;
    #pragma unroll
    for (int i = 0; i < 32; i += 8)
        tile[threadIdx.y + i][threadIdx.x] = src[(size_t)(by + threadIdx.y + i) * C + x];
    __syncthreads();
    int x2 = by + threadIdx.x;
    #pragma unroll
    for (int i = 0; i < 32; i += 8)
        dst[(size_t)(bx + threadIdx.y + i) * R + x2] = __float2half_rn(tile[threadIdx.x][threadIdx.y + i]);
}

__global__ void round_kernel(const float* __restrict__ src, __half* __restrict__ dst, int n) {
    int i = blockIdx.x * blockDim.x + threadIdx.x;
    if (i < n) dst[i] = __float2half_rn(src[i]);
}
__global__ void concat3_kernel(const float* __restrict__ a, const float* __restrict__ b,
                               const float* __restrict__ c, float* __restrict__ dst) {
    int i = blockIdx.x * blockDim.x + threadIdx.x;
    if (i < D) dst[i] = a[i];
    else if (i < 2 * D) dst[i] = b[i - D];
    else if (i < 3 * D) dst[i] = c[i - 2 * D];
}
__global__ void concat2_kernel(const float* __restrict__ a, const float* __restrict__ b,
                               float* __restrict__ dst) {
    int i = blockIdx.x * blockDim.x + threadIdx.x;
    if (i < D) dst[i] = a[i];
    else if (i < 2 * D) dst[i] = b[i - D];
}

// =======================================================================================
// fp16 mma.sync GEMM (unchanged from R6): BM=BN=128, BK=32, 4-stage cp.async, ldmatrix.
// =======================================================================================
#define WS     20
#define STAGES 4
#define TILEWW (128 * WS)

template<int ACT, bool RES, bool OUTH>
__global__ __launch_bounds__(256)
void gemm_mma(const __half* __restrict__ A, const __half* __restrict__ Bt,
              const float* __restrict__ bias, const float* __restrict__ res,
              void* __restrict__ Cv, int M, int N, int K) {
    extern __shared__ uint32_t smw[];

    const int tid  = threadIdx.x;
    const int lane = tid & 31, wid = tid >> 5;
    const int warp_m = wid & 1, warp_n = wid >> 1;
    const int bm = blockIdx.y * 128, bn = blockIdx.x * 128;
    const uint32_t sbase = smem_u32(smw);

    const int r0l = tid >> 2, subl = tid & 3;
    const __half* Ag = A + (size_t)(bm + r0l) * K + subl * 8;
    const __half* Bg = Bt + (size_t)(bn + r0l) * K + subl * 8;
    const uint32_t adst0 = sbase + (uint32_t)(r0l * WS + subl * 4) * 4u;
    const uint32_t bdst0 = sbase + (uint32_t)(STAGES * TILEWW + r0l * WS + subl * 4) * 4u;

    const int nt = K >> 5;

    auto prefetch = [&](int kt) {
        int s = kt % STAGES;
        uint32_t ad = adst0 + (uint32_t)(s * TILEWW) * 4u;
        uint32_t bd = bdst0 + (uint32_t)(s * TILEWW) * 4u;
        const __half* ag = Ag + kt * 32;
        const __half* bg = Bg + kt * 32;
        cp_async16(ad, ag);
        cp_async16(ad + (uint32_t)(64 * WS) * 4u, ag + (size_t)64 * K);
        cp_async16(bd, bg);
        cp_async16(bd + (uint32_t)(64 * WS) * 4u, bg + (size_t)64 * K);
    };

    float acc[4][4][4];
    #pragma unroll
    for (int mi = 0; mi < 4; mi++)
        #pragma unroll
        for (int ni = 0; ni < 4; ni++)
            #pragma unroll
            for (int e = 0; e < 4; e++) acc[mi][ni][e] = 0.0f;

    #pragma unroll
    for (int s = 0; s < STAGES - 1; s++) { prefetch(s); cp_commit(); }

    const uint32_t a_l = (uint32_t)((warp_m * 64 + (lane & 15)) * WS) * 4u + (uint32_t)((lane >> 4) * 16);
    const uint32_t b_l = (uint32_t)(STAGES * TILEWW) * 4u +
                         (uint32_t)((warp_n * 32 + (lane & 7) + ((lane >> 4) << 3)) * WS) * 4u +
                         (uint32_t)(((lane >> 3) & 1) * 16);

    for (int kt = 0; kt < nt; kt++) {
        cp_wait<STAGES - 2>();
        __syncthreads();
        if (kt + STAGES - 1 < nt) prefetch(kt + STAGES - 1);
        cp_commit();

        int s = kt % STAGES;
        const uint32_t soff = (uint32_t)(s * TILEWW) * 4u;
        const uint32_t abase_s = sbase + soff + a_l;
        const uint32_t bbase_s = sbase + soff + b_l;

        #pragma unroll
        for (int ks = 0; ks < 2; ks++) {
            const uint32_t koff = (uint32_t)(ks * 32);
            uint32_t af[4][4], bf[4][2];
            #pragma unroll
            for (int mi = 0; mi < 4; mi++)
                ldm_x4(af[mi][0], af[mi][1], af[mi][2], af[mi][3],
                       abase_s + (uint32_t)(mi * 16 * WS) * 4u + koff);
            ldm_x4(bf[0][0], bf[0][1], bf[1][0], bf[1][1], bbase_s + koff);
            ldm_x4(bf[2][0], bf[2][1], bf[3][0], bf[3][1],
                   bbase_s + (uint32_t)(16 * WS) * 4u + koff);
            #pragma unroll
            for (int mi = 0; mi < 4; mi++)
                #pragma unroll
                for (int ni = 0; ni < 4; ni++)
                    mma_f16(acc[mi][ni], af[mi], bf[ni]);
        }
    }

    const int lr = lane >> 2, lc = lane & 3;
    #pragma unroll
    for (int mi = 0; mi < 4; mi++) {
        int r0 = bm + warp_m * 64 + mi * 16 + lr;
        #pragma unroll
        for (int ni = 0; ni < 4; ni++) {
            int c0 = bn + warp_n * 32 + ni * 8 + 2 * lc;
            float b0 = bias[c0], b1 = bias[c0 + 1];
            float v00 = acc[mi][ni][0] + b0, v01 = acc[mi][ni][1] + b1;
            float v10 = acc[mi][ni][2] + b0, v11 = acc[mi][ni][3] + b1;
            if (ACT == 1) { v00 = silu_f(v00); v01 = silu_f(v01); v10 = silu_f(v10); v11 = silu_f(v11); }
            if (RES) {
                const float2 rA = *(const float2*)(res + (size_t)r0 * N + c0);
                const float2 rB = *(const float2*)(res + (size_t)(r0 + 8) * N + c0);
                v00 += rA.x; v01 += rA.y; v10 += rB.x; v11 += rB.y;
            }
            if (OUTH) {
                __half* Ch = (__half*)Cv;
                uint32_t p0 = packh2(v00, v01), p1 = packh2(v10, v11);
                *(uint32_t*)(Ch + (size_t)r0 * N + c0)       = p0;
                *(uint32_t*)(Ch + (size_t)(r0 + 8) * N + c0) = p1;
            } else {
                float* Cf = (float*)Cv;
                *(float2*)(Cf + (size_t)r0 * N + c0)       = make_float2(v00, v01);
                *(float2*)(Cf + (size_t)(r0 + 8) * N + c0) = make_float2(v10, v11);
            }
        }
    }
}

// =======================================================================================
// fp16 tensor-core flash attention (unchanged from R6).
// =======================================================================================
#define KVSTR_B 144
#define KTILE_B (64 * KVSTR_B)

__global__ __launch_bounds__(256)
void attn_tc(const __half* __restrict__ Q, int ldq,
             const __half* __restrict__ Kg, const __half* __restrict__ Vg, int ldkv,
             const float* __restrict__ xres, float* __restrict__ out,
             int Tq, int Tkv) {
    extern __shared__ uint32_t smw[];
    const uint32_t sbase = smem_u32(smw);

    const int tid = threadIdx.x;
    const int lane = tid & 31, wid = tid >> 5;
    const int lr = lane >> 2, lc = lane & 3;
    const int h = blockIdx.y, b = blockIdx.z;
    const int brow = b * Tq + blockIdx.x * 128;
    const int m0 = wid * 16;

    const __half* Kb = Kg + (size_t)b * Tkv * ldkv + h * HS;
    const __half* Vb = Vg + (size_t)b * Tkv * ldkv + h * HS;

    const float SC2 = 0.125f * 1.4426950408889634f;
    uint32_t qf[4][4];
    {
        const __half* Qp = Q + (size_t)(brow + m0) * ldq + h * HS;
        #pragma unroll
        for (int ks = 0; ks < 4; ks++) {
            int c = ks * 16 + 2 * lc;
            #pragma unroll
            for (int e = 0; e < 4; e++) {
                int rr = (e & 1) ? lr + 8 : lr;
                int cc = c + ((e >> 1) ? 8 : 0);
                __half2 hv = *(const __half2*)(Qp + (size_t)rr * ldq + cc);
                float2 f = __half22float2(hv);
                qf[ks][e] = packh2(f.x * SC2, f.y * SC2);
            }
        }
    }

    const int rl = lane & 7;
    const uint32_t loff_k = (uint32_t)(rl * KVSTR_B + ((lane >> 3) * 16));
    const uint32_t loff_v = (uint32_t)(((((lane >> 3) & 1) * 8 + rl) * KVSTR_B) + ((lane >> 4) * 16));

    const int lrow = tid >> 3, lsub = tid & 7;
    auto prefetch = [&](int kt) {
        int buf = kt & 1;
        uint32_t kdst = sbase + buf * KTILE_B + lrow * KVSTR_B + lsub * 16;
        uint32_t vdst = kdst + 2 * KTILE_B;
        const __half* kp = Kb + (size_t)(kt * 64 + lrow) * ldkv + lsub * 8;
        const __half* vp = Vb + (size_t)(kt * 64 + lrow) * ldkv + lsub * 8;
        cp_async16(kdst, kp);
        cp_async16(kdst + 32 * KVSTR_B, kp + (size_t)32 * ldkv);
        cp_async16(vdst, vp);
        cp_async16(vdst + 32 * KVSTR_B, vp + (size_t)32 * ldkv);
    };

    float oacc[8][4];
    #pragma unroll
    for (int i = 0; i < 8; i++)
        #pragma unroll
        for (int e = 0; e < 4; e++) oacc[i][e] = 0.0f;
    float mstate0 = -1e30f, mstate1 = -1e30f, l0 = 0.0f, l1 = 0.0f;

    const int nt = Tkv >> 6;
    prefetch(0); cp_commit();

    for (int kt = 0; kt < nt; kt++) {
        if (kt + 1 < nt) { prefetch(kt + 1); cp_commit(); cp_wait<1>(); }
        else             { cp_wait<0>(); }
        __syncthreads();

        const uint32_t kbase = sbase + (kt & 1) * KTILE_B;
        const uint32_t vbase = kbase + 2 * KTILE_B;

        float sacc[8][4];
        #pragma unroll
        for (int nf = 0; nf < 8; nf++)
            #pragma unroll
            for (int e = 0; e < 4; e++) sacc[nf][e] = 0.0f;

        #pragma unroll
        for (int nf = 0; nf < 8; nf++) {
            uint32_t k0, k1, k2, k3, k4, k5, k6, k7;
            uint32_t base = kbase + nf * (8 * KVSTR_B) + loff_k;
            ldm_x4(k0, k1, k2, k3, base);
            ldm_x4(k4, k5, k6, k7, base + 64);
            uint32_t bf[2];
            bf[0] = k0; bf[1] = k1; mma_f16(sacc[nf], qf[0], bf);
            bf[0] = k2; bf[1] = k3; mma_f16(sacc[nf], qf[1], bf);
            bf[0] = k4; bf[1] = k5; mma_f16(sacc[nf], qf[2], bf);
            bf[0] = k6; bf[1] = k7; mma_f16(sacc[nf], qf[3], bf);
        }

        float mx0 = -1e30f, mx1 = -1e30f;
        #pragma unroll
        for (int nf = 0; nf < 8; nf++) {
            mx0 = fmaxf(mx0, fmaxf(sacc[nf][0], sacc[nf][1]));
            mx1 = fmaxf(mx1, fmaxf(sacc[nf][2], sacc[nf][3]));
        }
        mx0 = fmaxf(mx0, __shfl_xor_sync(0xffffffffu, mx0, 1));
        mx0 = fmaxf(mx0, __shfl_xor_sync(0xffffffffu, mx0, 2));
        mx1 = fmaxf(mx1, __shfl_xor_sync(0xffffffffu, mx1, 1));
        mx1 = fmaxf(mx1, __shfl_xor_sync(0xffffffffu, mx1, 2));
        float mn0 = fmaxf(mstate0, mx0), mn1 = fmaxf(mstate1, mx1);
        float corr0 = exp2f(mstate0 - mn0), corr1 = exp2f(mstate1 - mn1);
        mstate0 = mn0; mstate1 = mn1;

        float sum0 = 0.0f, sum1 = 0.0f;
        #pragma unroll
        for (int nf = 0; nf < 8; nf++) {
            sacc[nf][0] = exp2f(sacc[nf][0] - mn0);
            sacc[nf][1] = exp2f(sacc[nf][1] - mn0);
            sacc[nf][2] = exp2f(sacc[nf][2] - mn1);
            sacc[nf][3] = exp2f(sacc[nf][3] - mn1);
            sum0 += sacc[nf][0] + sacc[nf][1];
            sum1 += sacc[nf][2] + sacc[nf][3];
        }
        sum0 += __shfl_xor_sync(0xffffffffu, sum0, 1);
        sum0 += __shfl_xor_sync(0xffffffffu, sum0, 2);
        sum1 += __shfl_xor_sync(0xffffffffu, sum1, 1);
        sum1 += __shfl_xor_sync(0xffffffffu, sum1, 2);
        l0 = l0 * corr0 + sum0;
        l1 = l1 * corr1 + sum1;
        #pragma unroll
        for (int nf = 0; nf < 8; nf++) {
            oacc[nf][0] *= corr0; oacc[nf][1] *= corr0;
            oacc[nf][2] *= corr1; oacc[nf][3] *= corr1;
        }

        #pragma unroll
        for (int kg = 0; kg < 4; kg++) {
            uint32_t af[4];
            af[0] = packh2(sacc[2*kg][0],   sacc[2*kg][1]);
            af[1] = packh2(sacc[2*kg][2],   sacc[2*kg][3]);
            af[2] = packh2(sacc[2*kg+1][0], sacc[2*kg+1][1]);
            af[3] = packh2(sacc[2*kg+1][2], sacc[2*kg+1][3]);
            #pragma unroll
            for (int nfp = 0; nfp < 4; nfp++) {
                uint32_t v0, v1, v2, v3;
                ldm_x4t(v0, v1, v2, v3, vbase + kg * (16 * KVSTR_B) + nfp * 32 + loff_v);
                uint32_t bf[2];
                bf[0] = v0; bf[1] = v1; mma_f16(oacc[2*nfp],     af, bf);
                bf[0] = v2; bf[1] = v3; mma_f16(oacc[2*nfp + 1], af, bf);
            }
        }
        __syncthreads();
    }

    float inv0 = 1.0f / l0, inv1 = 1.0f / l1;
    int row0 = brow + m0 + lr, row1 = row0 + 8;
    #pragma unroll
    for (int nf = 0; nf < 8; nf++) {
        int col = h * HS + nf * 8 + 2 * lc;
        float2 rA = *(const float2*)(xres + (size_t)row0 * D + col);
        float2 rB = *(const float2*)(xres + (size_t)row1 * D + col);
        *(float2*)(out + (size_t)row0 * D + col) =
            make_float2(rA.x + oacc[nf][0] * inv0, rA.y + oacc[nf][1] * inv0);
        *(float2*)(out + (size_t)row1 * D + col) =
            make_float2(rB.x + oacc[nf][2] * inv1, rB.y + oacc[nf][3] * inv1);
    }
}

// ---------------- host launch (multi-stream overlap inside the graph) ----------------
extern "C" void kernel_launch(void* const* d_in, const int* in_sizes, int n_in,
                              void* d_out, int out_size) {
    const float* x0    = (const float*)d_in[0];
    const float* ctx   = (const float*)d_in[1];
    const float* ln1_w = (const float*)d_in[2];
    const float* ln1_b = (const float*)d_in[3];
    const float* sWq   = (const float*)d_in[4];
    const float* sbq   = (const float*)d_in[5];
    const float* sWk   = (const float*)d_in[6];
    const float* sbk   = (const float*)d_in[7];
    const float* sWv   = (const float*)d_in[8];
    const float* sbv   = (const float*)d_in[9];
    const float* ln2_w = (const float*)d_in[10];
    const float* ln2_b = (const float*)d_in[11];
    const float* cWq   = (const float*)d_in[12];
    const float* cbq   = (const float*)d_in[13];
    const float* cWk   = (const float*)d_in[14];
    const float* cbk   = (const float*)d_in[15];
    const float* cWv   = (const float*)d_in[16];
    const float* cbv   = (const float*)d_in[17];
    const float* ln3_w = (const float*)d_in[18];
    const float* ln3_b = (const float*)d_in[19];
    const float* W1    = (const float*)d_in[20];
    const float* b1    = (const float*)d_in[21];
    const float* W2    = (const float*)d_in[22];
    const float* b2    = (const float*)d_in[23];
    float* outp = (float*)d_out;

    __half *ln, *q, *qkv, *kvc, *ctr, *ffh, *wts, *wtc, *w1t, *w2t;
    float *x1, *x2, *bqkv, *bkvc;
    cudaGetSymbolAddress((void**)&ln,   g_ln);
    cudaGetSymbolAddress((void**)&q,    g_q);
    cudaGetSymbolAddress((void**)&qkv,  g_qkv);
    cudaGetSymbolAddress((void**)&kvc,  g_kvc);
    cudaGetSymbolAddress((void**)&x1,   g_x1);
    cudaGetSymbolAddress((void**)&x2,   g_x2);
    cudaGetSymbolAddress((void**)&ctr,  g_ctx);
    cudaGetSymbolAddress((void**)&ffh,  g_ffh);
    cudaGetSymbolAddress((void**)&wts,  g_wts);
    cudaGetSymbolAddress((void**)&wtc,  g_wtc);
    cudaGetSymbolAddress((void**)&w1t,  g_w1t);
    cudaGetSymbolAddress((void**)&w2t,  g_w2t);
    cudaGetSymbolAddress((void**)&bqkv, g_bqkv);
    cudaGetSymbolAddress((void**)&bkvc, g_bkvc);

    const int SMEM_GEMM = STAGES * TILEWW * 2 * 4;   // 81920 B
    const int SMEM_ATTN = 4 * KTILE_B;               // 36864 B

    // one-time setup (runs uncaptured on first correctness call)
    static cudaStream_t s1 = nullptr;
    static cudaEvent_t eFork, eW1, eW2, eKV, eW3;
    static bool inited = false;
    if (!inited) {
        cudaStreamCreateWithFlags(&s1, cudaStreamNonBlocking);
        cudaEventCreateWithFlags(&eFork, cudaEventDisableTiming);
        cudaEventCreateWithFlags(&eW1,   cudaEventDisableTiming);
        cudaEventCreateWithFlags(&eW2,   cudaEventDisableTiming);
        cudaEventCreateWithFlags(&eKV,   cudaEventDisableTiming);
        cudaEventCreateWithFlags(&eW3,   cudaEventDisableTiming);
        cudaFuncSetAttribute(gemm_mma<0, false, true >, cudaFuncAttributeMaxDynamicSharedMemorySize, SMEM_GEMM);
        cudaFuncSetAttribute(gemm_mma<1, false, true >, cudaFuncAttributeMaxDynamicSharedMemorySize, SMEM_GEMM);
        cudaFuncSetAttribute(gemm_mma<0, true,  false>, cudaFuncAttributeMaxDynamicSharedMemorySize, SMEM_GEMM);
        cudaFuncSetAttribute(attn_tc, cudaFuncAttributeMaxDynamicSharedMemorySize, SMEM_ATTN);
        inited = true;
    }

    dim3 gqkv (3 * D / 128, MQ / 128);   // (18, 64)
    dim3 gq   (D / 128, MQ / 128);       // (6, 64)
    dim3 gkvc (2 * D / 128, MKV / 128);  // (12, 16)
    dim3 gff1 (FFD / 128, MQ / 128);     // (24, 64)
    dim3 gff2 (D / 128, MQ / 128);       // (6, 64)

    // ---- fork side stream (all input-only work) ----
    cudaEventRecord(eFork, 0);
    cudaStreamWaitEvent(s1, eFork, 0);

    // side stream: self-attn weight prep -> eW1
    concat3_kernel<<<9, 256, 0, s1>>>(sbq, sbk, sbv, bqkv);
    repack_kernel<<<(3 * DD + 255) / 256, 256, 0, s1>>>(sWq, sWk, sWv, wts);
    cudaEventRecord(eW1, s1);
    // side stream: cross-attn prep + KV gemm -> eW2, eKV
    round_kernel<<<(MKV * D + 255) / 256, 256, 0, s1>>>(ctx, ctr, MKV * D);
    repack_kernel<<<(3 * DD + 255) / 256, 256, 0, s1>>>(cWq, cWk, cWv, wtc);
    concat2_kernel<<<6, 256, 0, s1>>>(cbk, cbv, bkvc);
    cudaEventRecord(eW2, s1);
    gemm_mma<0, false, true><<<gkvc, 256, SMEM_GEMM, s1>>>(ctr, wtc + DD, bkvc, nullptr, kvc, MKV, 2 * D, D);
    cudaEventRecord(eKV, s1);
    // side stream: FFN weight transposes -> eW3
    transpose_kernel<<<dim3(FFD / 32, D / 32), dim3(32, 8), 0, s1>>>(W1, w1t, D, FFD);
    transpose_kernel<<<dim3(D / 32, FFD / 32), dim3(32, 8), 0, s1>>>(W2, w2t, FFD, D);
    cudaEventRecord(eW3, s1);

    // ---- main stream: block 1 (self attention, fused QKV) ----
    ln_kernel<<<MQ / 8, 256>>>(x0, ln1_w, ln1_b, ln);
    cudaStreamWaitEvent(0, eW1, 0);
    gemm_mma<0, false, true><<<gqkv, 256, SMEM_GEMM>>>(ln, wts, bqkv, nullptr, qkv, MQ, 3 * D, D);
    attn_tc<<<dim3(TT / 128, HH, BB), 256, SMEM_ATTN>>>(qkv, 3 * D, qkv + D, qkv + 2 * D, 3 * D,
                                                        x0, x1, TT, TT);

    // ---- block 2: cross attention ----
    ln_kernel<<<MQ / 8, 256>>>(x1, ln2_w, ln2_b, ln);
    cudaStreamWaitEvent(0, eW2, 0);
    gemm_mma<0, false, true><<<gq, 256, SMEM_GEMM>>>(ln, wtc, cbq, nullptr, q, MQ, D, D);
    cudaStreamWaitEvent(0, eKV, 0);
    attn_tc<<<dim3(TT / 128, HH, BB), 256, SMEM_ATTN>>>(q, D, kvc, kvc + D, 2 * D,
                                                        x1, x2, TT, TCC);

    // ---- block 3: FFN ----
    ln_kernel<<<MQ / 8, 256>>>(x2, ln3_w, ln3_b, ln);
    cudaStreamWaitEvent(0, eW3, 0);
    gemm_mma<1, false, true ><<<gff1, 256, SMEM_GEMM>>>(ln,  w1t, b1, nullptr, ffh,  MQ, FFD, D);
    gemm_mma<0, true,  false><<<gff2, 256, SMEM_GEMM>>>(ffh, w2t, b2, x2,      outp, MQ, D, FFD);
}